// round 1
// baseline (speedup 1.0000x reference)
#include <cuda_runtime.h>

#define DIMC 256
#define RESV 256
#define H2 128
#define HEADS 8
#define HD 32
#define NPIX 64
#define NWIN 512
#define PIXTOT (NWIN * NPIX)   // 32768
#define ATTN_SCALE 0.17677669529663687f
#define SROW 68                // padded smem row stride (floats), keeps 16B align

// ---------------- scratch (static device allocations; no cudaMalloc) -------
__device__ float g_ll[2 * DIMC * H2 * H2];
__device__ float g_lh[2 * DIMC * H2 * H2];
__device__ float g_hl[2 * DIMC * H2 * H2];
__device__ float g_hh[2 * DIMC * H2 * H2];
__device__ float g_att[DIMC * PIXTOT];    // relu(attention out), [c][pix]
__device__ float g_proj[DIMC * PIXTOT];   // proj out, [o][pix]
__device__ float g_bias[HEADS * NPIX * NPIX];

// ---------------- K0: expand attention bias table ---------------------------
__global__ void bias_kernel(const float* __restrict__ ab, const int* __restrict__ bidx) {
    int i = blockIdx.x * 256 + threadIdx.x;     // 32768 total
    int h = i >> 12;
    g_bias[i] = ab[h * 64 + bidx[i & 4095]];
}

// ---------------- K1: wavelet transform (depthwise 2x2 stride 2) -----------
__global__ void wt_kernel(const float* __restrict__ x, const float* __restrict__ wt) {
    int xo = threadIdx.x;          // 0..127
    int y  = blockIdx.x;           // 0..127
    int bc = blockIdx.y;           // 0..511 (b*256 + c)
    int c  = bc & 255;

    const float4 f0 = __ldg((const float4*)&wt[(4 * c + 0) * 4]);
    const float4 f1 = __ldg((const float4*)&wt[(4 * c + 1) * 4]);
    const float4 f2 = __ldg((const float4*)&wt[(4 * c + 2) * 4]);
    const float4 f3 = __ldg((const float4*)&wt[(4 * c + 3) * 4]);

    int ib = (bc * RESV + 2 * y) * RESV + 2 * xo;
    float2 p0 = *(const float2*)&x[ib];
    float2 p1 = *(const float2*)&x[ib + RESV];

    int ob = (bc * H2 + y) * H2 + xo;
    g_ll[ob] = p0.x * f0.x + p0.y * f0.y + p1.x * f0.z + p1.y * f0.w;
    g_lh[ob] = p0.x * f1.x + p0.y * f1.y + p1.x * f1.z + p1.y * f1.w;
    g_hl[ob] = p0.x * f2.x + p0.y * f2.y + p1.x * f2.z + p1.y * f2.w;
    g_hh[ob] = p0.x * f3.x + p0.y * f3.y + p1.x * f3.z + p1.y * f3.w;
}

// ---------------- K2: per-window attention over 8 sequential heads ----------
__global__ __launch_bounds__(256) void attn_kernel(
    const float* __restrict__ dww, const float* __restrict__ dwb) {
    __shared__ float k_s[HD * SROW];
    __shared__ float v_s[HD * SROW];
    __shared__ float q_s[HD * SROW];
    __shared__ float R[NPIX * SROW];     // union: (lh_s + w_s) during conv, attn_s after

    float* lh_s   = R;                   // HD*SROW floats
    float* w_s    = R + HD * SROW;       // 800 floats
    float* attn_s = R;                   // NPIX*SROW floats

    const int t  = threadIdx.x;
    const int w  = blockIdx.x;
    const int b  = w >> 8;
    const int wy = (w >> 4) & 15;
    const int wx = w & 15;
    const int dl = t >> 3;               // 0..31
    const int py = t & 7;                // 0..7

    for (int h = 0; h < HEADS; ++h) {
        // ---- load lh / hl / ll window slices ----
        {
            int ch   = b * DIMC + h * HD + dl;
            int base = (ch * H2 + wy * 8 + py) * H2 + wx * 8;
            int o0   = dl * SROW + py * 8;

            float4 a0 = *(const float4*)&g_lh[base];
            float4 a1 = *(const float4*)&g_lh[base + 4];
            *(float4*)&lh_s[o0]     = a0;
            *(float4*)&lh_s[o0 + 4] = a1;

            float4 b0 = *(const float4*)&g_hl[base];
            float4 b1 = *(const float4*)&g_hl[base + 4];
            *(float4*)&k_s[o0]     = b0;
            *(float4*)&k_s[o0 + 4] = b1;

            float4 c0 = *(const float4*)&g_ll[base];
            float4 c1 = *(const float4*)&g_ll[base + 4];
            if (h == 0) {
                *(float4*)&v_s[o0]     = c0;
                *(float4*)&v_s[o0 + 4] = c1;
            } else {  // v = prev attention output (in q_s) + ll slice
                v_s[o0 + 0] = q_s[o0 + 0] + c0.x;
                v_s[o0 + 1] = q_s[o0 + 1] + c0.y;
                v_s[o0 + 2] = q_s[o0 + 2] + c0.z;
                v_s[o0 + 3] = q_s[o0 + 3] + c0.w;
                v_s[o0 + 4] = q_s[o0 + 4] + c1.x;
                v_s[o0 + 5] = q_s[o0 + 5] + c1.y;
                v_s[o0 + 6] = q_s[o0 + 6] + c1.z;
                v_s[o0 + 7] = q_s[o0 + 7] + c1.w;
            }
        }
        for (int i = t; i < HD * 25; i += 256) w_s[i] = dww[h * HD * 25 + i];
        __syncthreads();

        // ---- q = depthwise 5x5 conv on lh (zero pad, per-window) ----
        {
            float accq[8];
            float bias0 = __ldg(&dwb[h * HD + dl]);
            #pragma unroll
            for (int px = 0; px < 8; ++px) accq[px] = bias0;
            #pragma unroll
            for (int u = 0; u < 5; ++u) {
                int yy = py + u - 2;
                if (yy >= 0 && yy < 8) {
                    #pragma unroll
                    for (int v = 0; v < 5; ++v) {
                        float wv = w_s[dl * 25 + u * 5 + v];
                        #pragma unroll
                        for (int px = 0; px < 8; ++px) {
                            int xx = px + v - 2;
                            if (xx >= 0 && xx < 8)
                                accq[px] += lh_s[dl * SROW + yy * 8 + xx] * wv;
                        }
                    }
                }
            }
            #pragma unroll
            for (int px = 0; px < 8; ++px) q_s[dl * SROW + py * 8 + px] = accq[px];
        }
        __syncthreads();

        // ---- attn[n][m] = softmax_m(q.k * scale + bias) ----
        {
            int n  = t >> 2;             // 0..63
            int mq = t & 3;              // 16 m's each
            float acc[16];
            #pragma unroll
            for (int i = 0; i < 16; ++i) acc[i] = 0.f;

            #pragma unroll 4
            for (int d2 = 0; d2 < HD; ++d2) {
                float qd = q_s[d2 * SROW + n];
                const float* kp = &k_s[d2 * SROW + mq * 16];
                float4 k0 = *(const float4*)(kp);
                float4 k1 = *(const float4*)(kp + 4);
                float4 k2 = *(const float4*)(kp + 8);
                float4 k3 = *(const float4*)(kp + 12);
                acc[0]  += qd * k0.x;  acc[1]  += qd * k0.y;
                acc[2]  += qd * k0.z;  acc[3]  += qd * k0.w;
                acc[4]  += qd * k1.x;  acc[5]  += qd * k1.y;
                acc[6]  += qd * k1.z;  acc[7]  += qd * k1.w;
                acc[8]  += qd * k2.x;  acc[9]  += qd * k2.y;
                acc[10] += qd * k2.z;  acc[11] += qd * k2.w;
                acc[12] += qd * k3.x;  acc[13] += qd * k3.y;
                acc[14] += qd * k3.z;  acc[15] += qd * k3.w;
            }

            const float* bptr = &g_bias[h * 4096 + n * 64 + mq * 16];
            float mx = -1e30f;
            #pragma unroll
            for (int mi = 0; mi < 16; ++mi) {
                acc[mi] = acc[mi] * ATTN_SCALE + __ldg(&bptr[mi]);
                mx = fmaxf(mx, acc[mi]);
            }
            mx = fmaxf(mx, __shfl_xor_sync(0xffffffffu, mx, 1));
            mx = fmaxf(mx, __shfl_xor_sync(0xffffffffu, mx, 2));
            float s = 0.f;
            #pragma unroll
            for (int mi = 0; mi < 16; ++mi) {
                float e = __expf(acc[mi] - mx);
                acc[mi] = e;
                s += e;
            }
            s += __shfl_xor_sync(0xffffffffu, s, 1);
            s += __shfl_xor_sync(0xffffffffu, s, 2);
            float inv = 1.f / s;
            #pragma unroll
            for (int mi = 0; mi < 16; ++mi)
                attn_s[n * SROW + mq * 16 + mi] = acc[mi] * inv;
        }
        __syncthreads();

        // ---- out[d][n] = sum_m v[d][m] * attn[n][m] ----
        {
            int d  = t >> 3;             // 0..31
            int nb = t & 7;              // n = nb + 8*ni
            float o[8];
            #pragma unroll
            for (int i = 0; i < 8; ++i) o[i] = 0.f;

            #pragma unroll
            for (int m = 0; m < 64; m += 4) {
                float4 v4 = *(const float4*)&v_s[d * SROW + m];
                #pragma unroll
                for (int ni = 0; ni < 8; ++ni) {
                    float4 a4 = *(const float4*)&attn_s[(nb + 8 * ni) * SROW + m];
                    o[ni] += v4.x * a4.x + v4.y * a4.y + v4.z * a4.z + v4.w * a4.w;
                }
            }
            #pragma unroll
            for (int ni = 0; ni < 8; ++ni) {
                int n = nb + 8 * ni;
                q_s[d * SROW + n] = o[ni];                               // feeds next head's v
                g_att[(h * HD + d) * PIXTOT + w * 64 + n] = fmaxf(o[ni], 0.f);  // relu, feeds proj
            }
        }
        __syncthreads();
    }
}

// ---------------- K3: proj GEMM  C[256,32768] = W[256,256] @ A + bias ------
__global__ __launch_bounds__(256) void proj_gemm(
    const float* __restrict__ Wm, const float* __restrict__ pb) {
    __shared__ float As[16 * SROW];   // As[k][m], m-tile 64
    __shared__ float Bs[16 * SROW];   // Bs[k][n], n-tile 64

    const int t  = threadIdx.x;
    const int n0 = blockIdx.x * 64;   // 0..511 tiles
    const int m0 = blockIdx.y * 64;   // 0..3 tiles
    const int tx = t & 15, ty = t >> 4;

    float acc[4][4];
    #pragma unroll
    for (int i = 0; i < 4; ++i)
        #pragma unroll
        for (int j = 0; j < 4; ++j) acc[i][j] = 0.f;

    for (int k0 = 0; k0 < 256; k0 += 16) {
        {
            int mm = t >> 2, kk = (t & 3) * 4;
            float4 wv = *(const float4*)&Wm[(m0 + mm) * 256 + k0 + kk];
            As[(kk + 0) * SROW + mm] = wv.x;
            As[(kk + 1) * SROW + mm] = wv.y;
            As[(kk + 2) * SROW + mm] = wv.z;
            As[(kk + 3) * SROW + mm] = wv.w;
        }
        {
            int kb = t >> 4, nn = (t & 15) * 4;
            *(float4*)&Bs[kb * SROW + nn] =
                *(const float4*)&g_att[(k0 + kb) * PIXTOT + n0 + nn];
        }
        __syncthreads();
        #pragma unroll
        for (int k = 0; k < 16; ++k) {
            float4 a  = *(const float4*)&As[k * SROW + ty * 4];
            float4 bb = *(const float4*)&Bs[k * SROW + tx * 4];
            acc[0][0] += a.x * bb.x; acc[0][1] += a.x * bb.y;
            acc[0][2] += a.x * bb.z; acc[0][3] += a.x * bb.w;
            acc[1][0] += a.y * bb.x; acc[1][1] += a.y * bb.y;
            acc[1][2] += a.y * bb.z; acc[1][3] += a.y * bb.w;
            acc[2][0] += a.z * bb.x; acc[2][1] += a.z * bb.y;
            acc[2][2] += a.z * bb.z; acc[2][3] += a.z * bb.w;
            acc[3][0] += a.w * bb.x; acc[3][1] += a.w * bb.y;
            acc[3][2] += a.w * bb.z; acc[3][3] += a.w * bb.w;
        }
        __syncthreads();
    }
    #pragma unroll
    for (int i = 0; i < 4; ++i) {
        float bias = __ldg(&pb[m0 + ty * 4 + i]);
        float4 r = make_float4(acc[i][0] + bias, acc[i][1] + bias,
                               acc[i][2] + bias, acc[i][3] + bias);
        *(float4*)&g_proj[(m0 + ty * 4 + i) * PIXTOT + n0 + tx * 4] = r;
    }
}

// ---------------- K4: inverse wavelet (transposed depthwise 2x2) ------------
__global__ void iwt_kernel(const float* __restrict__ iwt, float* __restrict__ out) {
    int xo = threadIdx.x;          // 0..127
    int y  = blockIdx.x;           // 0..127
    int bc = blockIdx.y;           // 0..511
    int b  = bc >> 8, c = bc & 255;

    int base = (bc * H2 + y) * H2 + xo;
    float lh = g_lh[base], hl = g_hl[base], hh = g_hh[base];

    int wy = y >> 3, pyy = y & 7, wx = xo >> 3, pxx = xo & 7;
    int wdx = (b * 16 + wy) * 16 + wx;
    float ll = g_proj[c * PIXTOT + wdx * 64 + pyy * 8 + pxx];

    // W(j,s,t) = iwt_filter[4c+j][0][s][t], used at output parity (Y&1, X&1)
    const float4 f0 = __ldg((const float4*)&iwt[(4 * c + 0) * 4]);
    const float4 f1 = __ldg((const float4*)&iwt[(4 * c + 1) * 4]);
    const float4 f2 = __ldg((const float4*)&iwt[(4 * c + 2) * 4]);
    const float4 f3 = __ldg((const float4*)&iwt[(4 * c + 3) * 4]);

    int ob = (bc * RESV + 2 * y) * RESV + 2 * xo;
    float2 r0 = make_float2(ll * f0.x + lh * f1.x + hl * f2.x + hh * f3.x,
                            ll * f0.y + lh * f1.y + hl * f2.y + hh * f3.y);
    float2 r1 = make_float2(ll * f0.z + lh * f1.z + hl * f2.z + hh * f3.z,
                            ll * f0.w + lh * f1.w + hl * f2.w + hh * f3.w);
    *(float2*)&out[ob]        = r0;
    *(float2*)&out[ob + RESV] = r1;
}

// ---------------- launch ----------------------------------------------------
extern "C" void kernel_launch(void* const* d_in, const int* in_sizes, int n_in,
                              void* d_out, int out_size) {
    const float* x    = (const float*)d_in[0];
    const float* wtf  = (const float*)d_in[1];
    const float* iwtf = (const float*)d_in[2];
    const float* dww  = (const float*)d_in[3];
    const float* dwb  = (const float*)d_in[4];
    const float* pw   = (const float*)d_in[5];
    const float* pb   = (const float*)d_in[6];
    const float* ab   = (const float*)d_in[7];
    const int*   bidx = (const int*)d_in[8];
    float* out = (float*)d_out;

    bias_kernel<<<128, 256>>>(ab, bidx);
    wt_kernel<<<dim3(128, 512), 128>>>(x, wtf);
    attn_kernel<<<512, 256>>>(dww, dwb);
    proj_gemm<<<dim3(512, 4), 256>>>(pw, pb);
    iwt_kernel<<<dim3(128, 512), 128>>>(iwtf, out);
}

// round 3
// speedup vs baseline: 1.0740x; 1.0740x over previous
#include <cuda_runtime.h>

#define DIMC 256
#define RESV 256
#define H2 128
#define HEADS 8
#define HD 32
#define NPIX 64
#define NWIN 512
#define PIXTOT (NWIN * NPIX)   // 32768
#define ATTN_SCALE 0.17677669529663687f
#define SROW 68                // padded smem row stride (floats)
#define BSROW 132              // padded stride for 128-wide B tile

// ---------------- scratch (static device allocations; no cudaMalloc) -------
__device__ float g_ll[2 * DIMC * H2 * H2];
__device__ float g_lh[2 * DIMC * H2 * H2];
__device__ float g_hl[2 * DIMC * H2 * H2];
__device__ float g_hh[2 * DIMC * H2 * H2];
__device__ float g_attn[NWIN * HEADS * NPIX * NPIX]; // softmax'd attn matrices
__device__ float g_att[DIMC * PIXTOT];    // relu(attention out), [c][pix]
__device__ float g_proj[DIMC * PIXTOT];   // proj out, [o][pix]
__device__ float g_bias[HEADS * NPIX * NPIX];

// ---------------- K0: expand attention bias table ---------------------------
__global__ void bias_kernel(const float* __restrict__ ab, const int* __restrict__ bidx) {
    int i = blockIdx.x * 256 + threadIdx.x;     // 32768 total
    int h = i >> 12;
    g_bias[i] = ab[h * 64 + bidx[i & 4095]];
}

// ---------------- K1: wavelet transform (depthwise 2x2 stride 2) -----------
__global__ void wt_kernel(const float* __restrict__ x, const float* __restrict__ wt) {
    int xo = threadIdx.x;          // 0..127
    int y  = blockIdx.x;           // 0..127
    int bc = blockIdx.y;           // 0..511 (b*256 + c)
    int c  = bc & 255;

    const float4 f0 = __ldg((const float4*)&wt[(4 * c + 0) * 4]);
    const float4 f1 = __ldg((const float4*)&wt[(4 * c + 1) * 4]);
    const float4 f2 = __ldg((const float4*)&wt[(4 * c + 2) * 4]);
    const float4 f3 = __ldg((const float4*)&wt[(4 * c + 3) * 4]);

    int ib = (bc * RESV + 2 * y) * RESV + 2 * xo;
    float2 p0 = *(const float2*)&x[ib];
    float2 p1 = *(const float2*)&x[ib + RESV];

    int ob = (bc * H2 + y) * H2 + xo;
    g_ll[ob] = p0.x * f0.x + p0.y * f0.y + p1.x * f0.z + p1.y * f0.w;
    g_lh[ob] = p0.x * f1.x + p0.y * f1.y + p1.x * f1.z + p1.y * f1.w;
    g_hl[ob] = p0.x * f2.x + p0.y * f2.y + p1.x * f2.z + p1.y * f2.w;
    g_hh[ob] = p0.x * f3.x + p0.y * f3.y + p1.x * f3.z + p1.y * f3.w;
}

// ---------------- K2a: attention matrices (all heads parallel) --------------
// One CTA per (window, head): q = dwconv5x5(lh), attn = softmax(qk*scale+bias)
__global__ __launch_bounds__(256) void attn_mat_kernel(
    const float* __restrict__ dww, const float* __restrict__ dwb) {
    __shared__ float lh_s[HD * SROW];
    __shared__ float k_s[HD * SROW];
    __shared__ float q_s[HD * SROW];
    __shared__ float w_s[HD * 25];

    const int t  = threadIdx.x;
    const int wh = blockIdx.x;           // 0..4095
    const int w  = wh >> 3;
    const int h  = wh & 7;
    const int b  = w >> 8;
    const int wy = (w >> 4) & 15;
    const int wx = w & 15;
    const int dl = t >> 3;               // 0..31
    const int py = t & 7;                // 0..7

    // ---- load lh / hl window slices ----
    {
        int ch   = b * DIMC + h * HD + dl;
        int base = (ch * H2 + wy * 8 + py) * H2 + wx * 8;
        int o0   = dl * SROW + py * 8;
        *(float4*)&lh_s[o0]     = *(const float4*)&g_lh[base];
        *(float4*)&lh_s[o0 + 4] = *(const float4*)&g_lh[base + 4];
        *(float4*)&k_s[o0]      = *(const float4*)&g_hl[base];
        *(float4*)&k_s[o0 + 4]  = *(const float4*)&g_hl[base + 4];
    }
    for (int i = t; i < HD * 25; i += 256) w_s[i] = dww[h * HD * 25 + i];
    __syncthreads();

    // ---- q = depthwise 5x5 conv on lh (zero pad, per-window) ----
    {
        float accq[8];
        float bias0 = __ldg(&dwb[h * HD + dl]);
        #pragma unroll
        for (int px = 0; px < 8; ++px) accq[px] = bias0;
        #pragma unroll
        for (int u = 0; u < 5; ++u) {
            int yy = py + u - 2;
            if (yy >= 0 && yy < 8) {
                #pragma unroll
                for (int v = 0; v < 5; ++v) {
                    float wv = w_s[dl * 25 + u * 5 + v];
                    #pragma unroll
                    for (int px = 0; px < 8; ++px) {
                        int xx = px + v - 2;
                        if (xx >= 0 && xx < 8)
                            accq[px] += lh_s[dl * SROW + yy * 8 + xx] * wv;
                    }
                }
            }
        }
        #pragma unroll
        for (int px = 0; px < 8; ++px) q_s[dl * SROW + py * 8 + px] = accq[px];
    }
    __syncthreads();

    // ---- attn[n][m] = softmax_m(q.k * scale + bias) -> global ----
    {
        int n  = t >> 2;             // 0..63
        int mq = t & 3;              // 16 m's each
        float acc[16];
        #pragma unroll
        for (int i = 0; i < 16; ++i) acc[i] = 0.f;

        #pragma unroll 4
        for (int d2 = 0; d2 < HD; ++d2) {
            float qd = q_s[d2 * SROW + n];
            const float* kp = &k_s[d2 * SROW + mq * 16];
            float4 k0 = *(const float4*)(kp);
            float4 k1 = *(const float4*)(kp + 4);
            float4 k2 = *(const float4*)(kp + 8);
            float4 k3 = *(const float4*)(kp + 12);
            acc[0]  += qd * k0.x;  acc[1]  += qd * k0.y;
            acc[2]  += qd * k0.z;  acc[3]  += qd * k0.w;
            acc[4]  += qd * k1.x;  acc[5]  += qd * k1.y;
            acc[6]  += qd * k1.z;  acc[7]  += qd * k1.w;
            acc[8]  += qd * k2.x;  acc[9]  += qd * k2.y;
            acc[10] += qd * k2.z;  acc[11] += qd * k2.w;
            acc[12] += qd * k3.x;  acc[13] += qd * k3.y;
            acc[14] += qd * k3.z;  acc[15] += qd * k3.w;
        }

        const float* bptr = &g_bias[h * 4096 + n * 64 + mq * 16];
        float mx = -1e30f;
        #pragma unroll
        for (int mi = 0; mi < 16; ++mi) {
            acc[mi] = acc[mi] * ATTN_SCALE + __ldg(&bptr[mi]);
            mx = fmaxf(mx, acc[mi]);
        }
        mx = fmaxf(mx, __shfl_xor_sync(0xffffffffu, mx, 1));
        mx = fmaxf(mx, __shfl_xor_sync(0xffffffffu, mx, 2));
        float s = 0.f;
        #pragma unroll
        for (int mi = 0; mi < 16; ++mi) {
            float e = __expf(acc[mi] - mx);
            acc[mi] = e;
            s += e;
        }
        s += __shfl_xor_sync(0xffffffffu, s, 1);
        s += __shfl_xor_sync(0xffffffffu, s, 2);
        float inv = 1.f / s;

        float* op = &g_attn[wh * 4096 + n * 64 + mq * 16];
        #pragma unroll
        for (int mi4 = 0; mi4 < 4; ++mi4) {
            float4 r = make_float4(acc[mi4 * 4 + 0] * inv, acc[mi4 * 4 + 1] * inv,
                                   acc[mi4 * 4 + 2] * inv, acc[mi4 * 4 + 3] * inv);
            *(float4*)&op[mi4 * 4] = r;
        }
    }
}

// ---------------- K2b: sequential AV chain per window -----------------------
__global__ __launch_bounds__(256) void attn_av_kernel() {
    __shared__ float v_s[HD * SROW];
    __shared__ float o_s[HD * SROW];
    __shared__ float attn_s[NPIX * SROW];

    const int t  = threadIdx.x;
    const int w  = blockIdx.x;
    const int b  = w >> 8;
    const int wy = (w >> 4) & 15;
    const int wx = w & 15;
    const int dl = t >> 3;               // 0..31
    const int py = t & 7;                // 0..7

    for (int h = 0; h < HEADS; ++h) {
        // ---- v = (prev out) + ll window slice ----
        {
            int ch   = b * DIMC + h * HD + dl;
            int base = (ch * H2 + wy * 8 + py) * H2 + wx * 8;
            int o0   = dl * SROW + py * 8;
            float4 c0 = *(const float4*)&g_ll[base];
            float4 c1 = *(const float4*)&g_ll[base + 4];
            if (h == 0) {
                *(float4*)&v_s[o0]     = c0;
                *(float4*)&v_s[o0 + 4] = c1;
            } else {
                v_s[o0 + 0] = o_s[o0 + 0] + c0.x;
                v_s[o0 + 1] = o_s[o0 + 1] + c0.y;
                v_s[o0 + 2] = o_s[o0 + 2] + c0.z;
                v_s[o0 + 3] = o_s[o0 + 3] + c0.w;
                v_s[o0 + 4] = o_s[o0 + 4] + c1.x;
                v_s[o0 + 5] = o_s[o0 + 5] + c1.y;
                v_s[o0 + 6] = o_s[o0 + 6] + c1.z;
                v_s[o0 + 7] = o_s[o0 + 7] + c1.w;
            }
        }
        // ---- stage attn tile (coalesced) ----
        {
            const float* ap = &g_attn[(w * 8 + h) * 4096];
            int n  = t >> 2;
            int m0 = (t & 3) * 16;
            #pragma unroll
            for (int i = 0; i < 4; ++i)
                *(float4*)&attn_s[n * SROW + m0 + i * 4] =
                    *(const float4*)&ap[n * 64 + m0 + i * 4];
        }
        __syncthreads();

        // ---- out[d][n] = sum_m v[d][m] * attn[n][m] ----
        {
            int d  = t >> 3;             // 0..31
            int nb = t & 7;              // n = nb + 8*ni
            float o[8];
            #pragma unroll
            for (int i = 0; i < 8; ++i) o[i] = 0.f;

            #pragma unroll
            for (int m = 0; m < 64; m += 4) {
                float4 v4 = *(const float4*)&v_s[d * SROW + m];
                #pragma unroll
                for (int ni = 0; ni < 8; ++ni) {
                    float4 a4 = *(const float4*)&attn_s[(nb + 8 * ni) * SROW + m];
                    o[ni] += v4.x * a4.x + v4.y * a4.y + v4.z * a4.z + v4.w * a4.w;
                }
            }
            #pragma unroll
            for (int ni = 0; ni < 8; ++ni)
                o_s[d * SROW + nb + 8 * ni] = o[ni];
        }
        __syncthreads();

        // ---- relu + fully coalesced write to g_att ----
        {
            int n = t & 63;
            int d0 = t >> 6;             // 0..3
            #pragma unroll
            for (int p = 0; p < 8; ++p) {
                int d = p * 4 + d0;
                g_att[(h * HD + d) * PIXTOT + w * 64 + n] =
                    fmaxf(o_s[d * SROW + n], 0.f);
            }
        }
        // next head's v-update reads o_s (written pre-barrier): safe.
    }
}

// ---------------- K3: proj GEMM  C[256,32768] = W[256,256] @ A + bias ------
// 64x128 tile, 4x8 per-thread micro-tile
__global__ __launch_bounds__(256) void proj_gemm(
    const float* __restrict__ Wm, const float* __restrict__ pb) {
    __shared__ float As[16 * SROW];    // As[k][m], m-tile 64
    __shared__ float Bs[16 * BSROW];   // Bs[k][n], n-tile 128

    const int t  = threadIdx.x;
    const int n0 = blockIdx.x * 128;   // 256 tiles
    const int m0 = blockIdx.y * 64;    // 4 tiles
    const int tx = t & 15, ty = t >> 4;

    float acc[4][8];
    #pragma unroll
    for (int i = 0; i < 4; ++i)
        #pragma unroll
        for (int j = 0; j < 8; ++j) acc[i][j] = 0.f;

    for (int k0 = 0; k0 < 256; k0 += 16) {
        {
            int mm = t >> 2, kk = (t & 3) * 4;
            float4 wv = *(const float4*)&Wm[(m0 + mm) * 256 + k0 + kk];
            As[(kk + 0) * SROW + mm] = wv.x;
            As[(kk + 1) * SROW + mm] = wv.y;
            As[(kk + 2) * SROW + mm] = wv.z;
            As[(kk + 3) * SROW + mm] = wv.w;
        }
        {
            int kb = t >> 4, nn = (t & 15) * 8;
            const float* gp = &g_att[(k0 + kb) * PIXTOT + n0 + nn];
            *(float4*)&Bs[kb * BSROW + nn]     = *(const float4*)gp;
            *(float4*)&Bs[kb * BSROW + nn + 4] = *(const float4*)(gp + 4);
        }
        __syncthreads();
        #pragma unroll
        for (int k = 0; k < 16; ++k) {
            float4 a  = *(const float4*)&As[k * SROW + ty * 4];
            float4 b0 = *(const float4*)&Bs[k * BSROW + tx * 4];
            float4 b1 = *(const float4*)&Bs[k * BSROW + 64 + tx * 4];
            acc[0][0] += a.x * b0.x; acc[0][1] += a.x * b0.y;
            acc[0][2] += a.x * b0.z; acc[0][3] += a.x * b0.w;
            acc[0][4] += a.x * b1.x; acc[0][5] += a.x * b1.y;
            acc[0][6] += a.x * b1.z; acc[0][7] += a.x * b1.w;
            acc[1][0] += a.y * b0.x; acc[1][1] += a.y * b0.y;
            acc[1][2] += a.y * b0.z; acc[1][3] += a.y * b0.w;
            acc[1][4] += a.y * b1.x; acc[1][5] += a.y * b1.y;
            acc[1][6] += a.y * b1.z; acc[1][7] += a.y * b1.w;
            acc[2][0] += a.z * b0.x; acc[2][1] += a.z * b0.y;
            acc[2][2] += a.z * b0.z; acc[2][3] += a.z * b0.w;
            acc[2][4] += a.z * b1.x; acc[2][5] += a.z * b1.y;
            acc[2][6] += a.z * b1.z; acc[2][7] += a.z * b1.w;
            acc[3][0] += a.w * b0.x; acc[3][1] += a.w * b0.y;
            acc[3][2] += a.w * b0.z; acc[3][3] += a.w * b0.w;
            acc[3][4] += a.w * b1.x; acc[3][5] += a.w * b1.y;
            acc[3][6] += a.w * b1.z; acc[3][7] += a.w * b1.w;
        }
        __syncthreads();
    }
    #pragma unroll
    for (int i = 0; i < 4; ++i) {
        float bias = __ldg(&pb[m0 + ty * 4 + i]);
        float* rp = &g_proj[(m0 + ty * 4 + i) * PIXTOT + n0];
        float4 r0 = make_float4(acc[i][0] + bias, acc[i][1] + bias,
                                acc[i][2] + bias, acc[i][3] + bias);
        float4 r1 = make_float4(acc[i][4] + bias, acc[i][5] + bias,
                                acc[i][6] + bias, acc[i][7] + bias);
        *(float4*)&rp[tx * 4]      = r0;
        *(float4*)&rp[64 + tx * 4] = r1;
    }
}

// ---------------- K4: inverse wavelet (transposed depthwise 2x2) ------------
__global__ void iwt_kernel(const float* __restrict__ iwt, float* __restrict__ out) {
    int xo = threadIdx.x;          // 0..127
    int y  = blockIdx.x;           // 0..127
    int bc = blockIdx.y;           // 0..511
    int b  = bc >> 8, c = bc & 255;

    int base = (bc * H2 + y) * H2 + xo;
    float lh = g_lh[base], hl = g_hl[base], hh = g_hh[base];

    int wy = y >> 3, pyy = y & 7, wx = xo >> 3, pxx = xo & 7;
    int wdx = (b * 16 + wy) * 16 + wx;
    float ll = g_proj[c * PIXTOT + wdx * 64 + pyy * 8 + pxx];

    const float4 f0 = __ldg((const float4*)&iwt[(4 * c + 0) * 4]);
    const float4 f1 = __ldg((const float4*)&iwt[(4 * c + 1) * 4]);
    const float4 f2 = __ldg((const float4*)&iwt[(4 * c + 2) * 4]);
    const float4 f3 = __ldg((const float4*)&iwt[(4 * c + 3) * 4]);

    int ob = (bc * RESV + 2 * y) * RESV + 2 * xo;
    float2 r0 = make_float2(ll * f0.x + lh * f1.x + hl * f2.x + hh * f3.x,
                            ll * f0.y + lh * f1.y + hl * f2.y + hh * f3.y);
    float2 r1 = make_float2(ll * f0.z + lh * f1.z + hl * f2.z + hh * f3.z,
                            ll * f0.w + lh * f1.w + hl * f2.w + hh * f3.w);
    *(float2*)&out[ob]        = r0;
    *(float2*)&out[ob + RESV] = r1;
}

// ---------------- launch ----------------------------------------------------
extern "C" void kernel_launch(void* const* d_in, const int* in_sizes, int n_in,
                              void* d_out, int out_size) {
    const float* x    = (const float*)d_in[0];
    const float* wtf  = (const float*)d_in[1];
    const float* iwtf = (const float*)d_in[2];
    const float* dww  = (const float*)d_in[3];
    const float* dwb  = (const float*)d_in[4];
    const float* pw   = (const float*)d_in[5];
    const float* pb   = (const float*)d_in[6];
    const float* ab   = (const float*)d_in[7];
    const int*   bidx = (const int*)d_in[8];
    float* out = (float*)d_out;

    bias_kernel<<<128, 256>>>(ab, bidx);
    wt_kernel<<<dim3(128, 512), 128>>>(x, wtf);
    attn_mat_kernel<<<4096, 256>>>(dww, dwb);
    attn_av_kernel<<<512, 256>>>();
    proj_gemm<<<dim3(256, 4), 256>>>(pw, pb);
    iwt_kernel<<<dim3(128, 512), 128>>>(iwtf, out);
}

// round 4
// speedup vs baseline: 1.2059x; 1.1228x over previous
#include <cuda_runtime.h>

#define DIMC 256
#define RESV 256
#define H2 128
#define HEADS 8
#define HD 32
#define NPIX 64
#define NWIN 512
#define PIXTOT (NWIN * NPIX)   // 32768
#define ATTN_SCALE 0.17677669529663687f
#define SROW 68                // padded smem row stride (floats)
#define BSROW 132              // padded stride for 128-wide B tile

// ---------------- scratch (static device allocations; no cudaMalloc) -------
__device__ float g_ll[2 * DIMC * H2 * H2];
__device__ float g_lh[2 * DIMC * H2 * H2];
__device__ float g_hl[2 * DIMC * H2 * H2];
__device__ float g_hh[2 * DIMC * H2 * H2];
__device__ float g_attn[NWIN * HEADS * NPIX * NPIX]; // softmax'd attn, [wh][m][n]
__device__ float g_att[DIMC * PIXTOT];    // relu(attention out), [c][pix]
__device__ float g_proj[DIMC * PIXTOT];   // proj out, [o][pix]
__device__ float g_bias[HEADS * NPIX * NPIX];

// ---------------- K0: expand attention bias table ---------------------------
__global__ void bias_kernel(const float* __restrict__ ab, const int* __restrict__ bidx) {
    int i = blockIdx.x * 256 + threadIdx.x;     // 32768 total
    int h = i >> 12;
    g_bias[i] = ab[h * 64 + bidx[i & 4095]];
}

// ---------------- K1: wavelet transform (depthwise 2x2 stride 2) -----------
__global__ void wt_kernel(const float* __restrict__ x, const float* __restrict__ wt) {
    int xo = threadIdx.x;          // 0..127
    int y  = blockIdx.x;           // 0..127
    int bc = blockIdx.y;           // 0..511 (b*256 + c)
    int c  = bc & 255;

    const float4 f0 = __ldg((const float4*)&wt[(4 * c + 0) * 4]);
    const float4 f1 = __ldg((const float4*)&wt[(4 * c + 1) * 4]);
    const float4 f2 = __ldg((const float4*)&wt[(4 * c + 2) * 4]);
    const float4 f3 = __ldg((const float4*)&wt[(4 * c + 3) * 4]);

    int ib = (bc * RESV + 2 * y) * RESV + 2 * xo;
    float2 p0 = *(const float2*)&x[ib];
    float2 p1 = *(const float2*)&x[ib + RESV];

    int ob = (bc * H2 + y) * H2 + xo;
    g_ll[ob] = p0.x * f0.x + p0.y * f0.y + p1.x * f0.z + p1.y * f0.w;
    g_lh[ob] = p0.x * f1.x + p0.y * f1.y + p1.x * f1.z + p1.y * f1.w;
    g_hl[ob] = p0.x * f2.x + p0.y * f2.y + p1.x * f2.z + p1.y * f2.w;
    g_hh[ob] = p0.x * f3.x + p0.y * f3.y + p1.x * f3.z + p1.y * f3.w;
}

// ---------------- K2a: attention matrices (all heads parallel) --------------
// One CTA per (window, head): q = dwconv5x5(lh), attn = softmax(qk*scale+bias)
// Output stored TRANSPOSED: g_attn[wh][m][n]
__global__ __launch_bounds__(256) void attn_mat_kernel(
    const float* __restrict__ dww, const float* __restrict__ dwb) {
    __shared__ float lh_s[HD * SROW];
    __shared__ float k_s[HD * SROW];
    __shared__ float q_s[HD * SROW];
    __shared__ float w_s[HD * 25];

    const int t  = threadIdx.x;
    const int wh = blockIdx.x;           // 0..4095
    const int w  = wh >> 3;
    const int h  = wh & 7;
    const int b  = w >> 8;
    const int wy = (w >> 4) & 15;
    const int wx = w & 15;
    const int dl = t >> 3;               // 0..31
    const int py = t & 7;                // 0..7

    // ---- load lh / hl window slices ----
    {
        int ch   = b * DIMC + h * HD + dl;
        int base = (ch * H2 + wy * 8 + py) * H2 + wx * 8;
        int o0   = dl * SROW + py * 8;
        *(float4*)&lh_s[o0]     = *(const float4*)&g_lh[base];
        *(float4*)&lh_s[o0 + 4] = *(const float4*)&g_lh[base + 4];
        *(float4*)&k_s[o0]      = *(const float4*)&g_hl[base];
        *(float4*)&k_s[o0 + 4]  = *(const float4*)&g_hl[base + 4];
    }
    for (int i = t; i < HD * 25; i += 256) w_s[i] = dww[h * HD * 25 + i];
    __syncthreads();

    // ---- q = depthwise 5x5 conv on lh (zero pad, per-window) ----
    {
        float accq[8];
        float bias0 = __ldg(&dwb[h * HD + dl]);
        #pragma unroll
        for (int px = 0; px < 8; ++px) accq[px] = bias0;
        #pragma unroll
        for (int u = 0; u < 5; ++u) {
            int yy = py + u - 2;
            if (yy >= 0 && yy < 8) {
                #pragma unroll
                for (int v = 0; v < 5; ++v) {
                    float wv = w_s[dl * 25 + u * 5 + v];
                    #pragma unroll
                    for (int px = 0; px < 8; ++px) {
                        int xx = px + v - 2;
                        if (xx >= 0 && xx < 8)
                            accq[px] += lh_s[dl * SROW + yy * 8 + xx] * wv;
                    }
                }
            }
        }
        #pragma unroll
        for (int px = 0; px < 8; ++px) q_s[dl * SROW + py * 8 + px] = accq[px];
    }
    __syncthreads();

    // ---- attn[n][m] = softmax_m(q.k * scale + bias) -> global (transposed) ----
    {
        int n  = t >> 2;             // 0..63
        int mq = t & 3;              // 16 m's each
        float acc[16];
        #pragma unroll
        for (int i = 0; i < 16; ++i) acc[i] = 0.f;

        #pragma unroll 4
        for (int d2 = 0; d2 < HD; ++d2) {
            float qd = q_s[d2 * SROW + n];
            const float* kp = &k_s[d2 * SROW + mq * 16];
            float4 k0 = *(const float4*)(kp);
            float4 k1 = *(const float4*)(kp + 4);
            float4 k2 = *(const float4*)(kp + 8);
            float4 k3 = *(const float4*)(kp + 12);
            acc[0]  += qd * k0.x;  acc[1]  += qd * k0.y;
            acc[2]  += qd * k0.z;  acc[3]  += qd * k0.w;
            acc[4]  += qd * k1.x;  acc[5]  += qd * k1.y;
            acc[6]  += qd * k1.z;  acc[7]  += qd * k1.w;
            acc[8]  += qd * k2.x;  acc[9]  += qd * k2.y;
            acc[10] += qd * k2.z;  acc[11] += qd * k2.w;
            acc[12] += qd * k3.x;  acc[13] += qd * k3.y;
            acc[14] += qd * k3.z;  acc[15] += qd * k3.w;
        }

        const float* bptr = &g_bias[h * 4096 + n * 64 + mq * 16];
        float mx = -1e30f;
        #pragma unroll
        for (int mi = 0; mi < 16; ++mi) {
            acc[mi] = acc[mi] * ATTN_SCALE + __ldg(&bptr[mi]);
            mx = fmaxf(mx, acc[mi]);
        }
        mx = fmaxf(mx, __shfl_xor_sync(0xffffffffu, mx, 1));
        mx = fmaxf(mx, __shfl_xor_sync(0xffffffffu, mx, 2));
        float s = 0.f;
        #pragma unroll
        for (int mi = 0; mi < 16; ++mi) {
            float e = __expf(acc[mi] - mx);
            acc[mi] = e;
            s += e;
        }
        s += __shfl_xor_sync(0xffffffffu, s, 1);
        s += __shfl_xor_sync(0xffffffffu, s, 2);
        float inv = 1.f / s;

        float* op = &g_attn[wh * 4096];
        #pragma unroll
        for (int mi = 0; mi < 16; ++mi)
            op[(mq * 16 + mi) * 64 + n] = acc[mi] * inv;   // [m][n]
    }
}

// ---------------- K2b: sequential AV chain per window -----------------------
// v_s/o_s: [d][m] contiguous (stride 64). attn_s: [m][n] contiguous.
// Register prefetch of next head's attn tile + ll slice hides gmem latency.
__global__ __launch_bounds__(256) void attn_av_kernel() {
    __shared__ float v_s[HD * NPIX];        // 8KB
    __shared__ float o_s[HD * NPIX];        // 8KB
    __shared__ float attn_s[NPIX * NPIX];   // 16KB

    const int t  = threadIdx.x;
    const int w  = blockIdx.x;
    const int b  = w >> 8;
    const int wy = (w >> 4) & 15;
    const int wx = w & 15;
    const int wp   = t >> 5;             // warp 0..7 -> d rows 4wp..4wp+3
    const int lane = t & 31;             // n and n+32

    float4 pa[4];   // prefetched attn chunk (chunks t, t+256, t+512, t+768)
    float4 pl[2];   // prefetched ll chunk  (chunks t, t+256)

    // ---- prologue: load head 0 ----
    {
        const float* ap = &g_attn[(w * 8 + 0) * 4096];
        #pragma unroll
        for (int i = 0; i < 4; ++i)
            pa[i] = *(const float4*)&ap[(t + 256 * i) * 4];
        #pragma unroll
        for (int i = 0; i < 2; ++i) {
            int c  = t + 256 * i;
            int d  = c >> 4;
            int m0 = (c & 15) * 4;               // py = m0>>3, px0 = m0&7
            int ch = b * DIMC + 0 * HD + d;
            pl[i] = *(const float4*)&g_ll[(ch * H2 + wy * 8 + (m0 >> 3)) * H2
                                          + wx * 8 + (m0 & 7)];
        }
    }

    for (int h = 0; h < HEADS; ++h) {
        __syncthreads();   // o_s (prev FMA) ready; attn_s/v_s free for overwrite

        // ---- phase 1: stage attn, build v, relu-store previous head's out ----
        #pragma unroll
        for (int i = 0; i < 4; ++i)
            *(float4*)&attn_s[(t + 256 * i) * 4] = pa[i];
        #pragma unroll
        for (int i = 0; i < 2; ++i) {
            int c = t + 256 * i;
            float4 v4 = pl[i];
            if (h > 0) {
                float4 o4 = *(const float4*)&o_s[c * 4];
                v4.x += o4.x; v4.y += o4.y; v4.z += o4.z; v4.w += o4.w;
                int d  = c >> 4;
                int m0 = (c & 15) * 4;
                float4 r = make_float4(fmaxf(o4.x, 0.f), fmaxf(o4.y, 0.f),
                                       fmaxf(o4.z, 0.f), fmaxf(o4.w, 0.f));
                *(float4*)&g_att[((h - 1) * HD + d) * PIXTOT + w * 64 + m0] = r;
            }
            *(float4*)&v_s[c * 4] = v4;
        }

        // ---- issue prefetch for head h+1 (consumed next phase 1) ----
        if (h < HEADS - 1) {
            const float* ap = &g_attn[(w * 8 + h + 1) * 4096];
            #pragma unroll
            for (int i = 0; i < 4; ++i)
                pa[i] = *(const float4*)&ap[(t + 256 * i) * 4];
            #pragma unroll
            for (int i = 0; i < 2; ++i) {
                int c  = t + 256 * i;
                int d  = c >> 4;
                int m0 = (c & 15) * 4;
                int ch = b * DIMC + (h + 1) * HD + d;
                pl[i] = *(const float4*)&g_ll[(ch * H2 + wy * 8 + (m0 >> 3)) * H2
                                              + wx * 8 + (m0 & 7)];
            }
        }
        __syncthreads();   // v_s / attn_s ready

        // ---- phase 2: out[d][n] = sum_m v[d][m] * attn_t[m][n] ----
        float acc[4][2];
        #pragma unroll
        for (int j = 0; j < 4; ++j) { acc[j][0] = 0.f; acc[j][1] = 0.f; }

        #pragma unroll
        for (int m = 0; m < 64; m += 4) {
            float4 a0 = *(const float4*)&v_s[(4 * wp + 0) * 64 + m];
            float4 a1 = *(const float4*)&v_s[(4 * wp + 1) * 64 + m];
            float4 a2 = *(const float4*)&v_s[(4 * wp + 2) * 64 + m];
            float4 a3 = *(const float4*)&v_s[(4 * wp + 3) * 64 + m];
            float b0l = attn_s[(m + 0) * 64 + lane];
            float b1l = attn_s[(m + 1) * 64 + lane];
            float b2l = attn_s[(m + 2) * 64 + lane];
            float b3l = attn_s[(m + 3) * 64 + lane];
            float b0h = attn_s[(m + 0) * 64 + lane + 32];
            float b1h = attn_s[(m + 1) * 64 + lane + 32];
            float b2h = attn_s[(m + 2) * 64 + lane + 32];
            float b3h = attn_s[(m + 3) * 64 + lane + 32];
            acc[0][0] += a0.x * b0l + a0.y * b1l + a0.z * b2l + a0.w * b3l;
            acc[1][0] += a1.x * b0l + a1.y * b1l + a1.z * b2l + a1.w * b3l;
            acc[2][0] += a2.x * b0l + a2.y * b1l + a2.z * b2l + a2.w * b3l;
            acc[3][0] += a3.x * b0l + a3.y * b1l + a3.z * b2l + a3.w * b3l;
            acc[0][1] += a0.x * b0h + a0.y * b1h + a0.z * b2h + a0.w * b3h;
            acc[1][1] += a1.x * b0h + a1.y * b1h + a1.z * b2h + a1.w * b3h;
            acc[2][1] += a2.x * b0h + a2.y * b1h + a2.z * b2h + a2.w * b3h;
            acc[3][1] += a3.x * b0h + a3.y * b1h + a3.z * b2h + a3.w * b3h;
        }
        #pragma unroll
        for (int j = 0; j < 4; ++j) {
            o_s[(4 * wp + j) * 64 + lane]      = acc[j][0];
            o_s[(4 * wp + j) * 64 + lane + 32] = acc[j][1];
        }
    }

    // ---- epilogue: relu-store head 7 output ----
    __syncthreads();
    #pragma unroll
    for (int i = 0; i < 2; ++i) {
        int c  = t + 256 * i;
        int d  = c >> 4;
        int m0 = (c & 15) * 4;
        float4 o4 = *(const float4*)&o_s[c * 4];
        float4 r = make_float4(fmaxf(o4.x, 0.f), fmaxf(o4.y, 0.f),
                               fmaxf(o4.z, 0.f), fmaxf(o4.w, 0.f));
        *(float4*)&g_att[(7 * HD + d) * PIXTOT + w * 64 + m0] = r;
    }
}

// ---------------- K3: proj GEMM  C[256,32768] = W[256,256] @ A + bias ------
// 64x128 tile, 4x8 per-thread micro-tile
__global__ __launch_bounds__(256) void proj_gemm(
    const float* __restrict__ Wm, const float* __restrict__ pb) {
    __shared__ float As[16 * SROW];    // As[k][m], m-tile 64
    __shared__ float Bs[16 * BSROW];   // Bs[k][n], n-tile 128

    const int t  = threadIdx.x;
    const int n0 = blockIdx.x * 128;   // 256 tiles
    const int m0 = blockIdx.y * 64;    // 4 tiles
    const int tx = t & 15, ty = t >> 4;

    float acc[4][8];
    #pragma unroll
    for (int i = 0; i < 4; ++i)
        #pragma unroll
        for (int j = 0; j < 8; ++j) acc[i][j] = 0.f;

    for (int k0 = 0; k0 < 256; k0 += 16) {
        {
            int mm = t >> 2, kk = (t & 3) * 4;
            float4 wv = *(const float4*)&Wm[(m0 + mm) * 256 + k0 + kk];
            As[(kk + 0) * SROW + mm] = wv.x;
            As[(kk + 1) * SROW + mm] = wv.y;
            As[(kk + 2) * SROW + mm] = wv.z;
            As[(kk + 3) * SROW + mm] = wv.w;
        }
        {
            int kb = t >> 4, nn = (t & 15) * 8;
            const float* gp = &g_att[(k0 + kb) * PIXTOT + n0 + nn];
            *(float4*)&Bs[kb * BSROW + nn]     = *(const float4*)gp;
            *(float4*)&Bs[kb * BSROW + nn + 4] = *(const float4*)(gp + 4);
        }
        __syncthreads();
        #pragma unroll
        for (int k = 0; k < 16; ++k) {
            float4 a  = *(const float4*)&As[k * SROW + ty * 4];
            float4 b0 = *(const float4*)&Bs[k * BSROW + tx * 4];
            float4 b1 = *(const float4*)&Bs[k * BSROW + 64 + tx * 4];
            acc[0][0] += a.x * b0.x; acc[0][1] += a.x * b0.y;
            acc[0][2] += a.x * b0.z; acc[0][3] += a.x * b0.w;
            acc[0][4] += a.x * b1.x; acc[0][5] += a.x * b1.y;
            acc[0][6] += a.x * b1.z; acc[0][7] += a.x * b1.w;
            acc[1][0] += a.y * b0.x; acc[1][1] += a.y * b0.y;
            acc[1][2] += a.y * b0.z; acc[1][3] += a.y * b0.w;
            acc[1][4] += a.y * b1.x; acc[1][5] += a.y * b1.y;
            acc[1][6] += a.y * b1.z; acc[1][7] += a.y * b1.w;
            acc[2][0] += a.z * b0.x; acc[2][1] += a.z * b0.y;
            acc[2][2] += a.z * b0.z; acc[2][3] += a.z * b0.w;
            acc[2][4] += a.z * b1.x; acc[2][5] += a.z * b1.y;
            acc[2][6] += a.z * b1.z; acc[2][7] += a.z * b1.w;
            acc[3][0] += a.w * b0.x; acc[3][1] += a.w * b0.y;
            acc[3][2] += a.w * b0.z; acc[3][3] += a.w * b0.w;
            acc[3][4] += a.w * b1.x; acc[3][5] += a.w * b1.y;
            acc[3][6] += a.w * b1.z; acc[3][7] += a.w * b1.w;
        }
        __syncthreads();
    }
    #pragma unroll
    for (int i = 0; i < 4; ++i) {
        float bias = __ldg(&pb[m0 + ty * 4 + i]);
        float* rp = &g_proj[(m0 + ty * 4 + i) * PIXTOT + n0];
        float4 r0 = make_float4(acc[i][0] + bias, acc[i][1] + bias,
                                acc[i][2] + bias, acc[i][3] + bias);
        float4 r1 = make_float4(acc[i][4] + bias, acc[i][5] + bias,
                                acc[i][6] + bias, acc[i][7] + bias);
        *(float4*)&rp[tx * 4]      = r0;
        *(float4*)&rp[64 + tx * 4] = r1;
    }
}

// ---------------- K4: inverse wavelet (transposed depthwise 2x2) ------------
__global__ void iwt_kernel(const float* __restrict__ iwt, float* __restrict__ out) {
    int xo = threadIdx.x;          // 0..127
    int y  = blockIdx.x;           // 0..127
    int bc = blockIdx.y;           // 0..511
    int b  = bc >> 8, c = bc & 255;

    int base = (bc * H2 + y) * H2 + xo;
    float lh = g_lh[base], hl = g_hl[base], hh = g_hh[base];

    int wy = y >> 3, pyy = y & 7, wx = xo >> 3, pxx = xo & 7;
    int wdx = (b * 16 + wy) * 16 + wx;
    float ll = g_proj[c * PIXTOT + wdx * 64 + pyy * 8 + pxx];

    const float4 f0 = __ldg((const float4*)&iwt[(4 * c + 0) * 4]);
    const float4 f1 = __ldg((const float4*)&iwt[(4 * c + 1) * 4]);
    const float4 f2 = __ldg((const float4*)&iwt[(4 * c + 2) * 4]);
    const float4 f3 = __ldg((const float4*)&iwt[(4 * c + 3) * 4]);

    int ob = (bc * RESV + 2 * y) * RESV + 2 * xo;
    float2 r0 = make_float2(ll * f0.x + lh * f1.x + hl * f2.x + hh * f3.x,
                            ll * f0.y + lh * f1.y + hl * f2.y + hh * f3.y);
    float2 r1 = make_float2(ll * f0.z + lh * f1.z + hl * f2.z + hh * f3.z,
                            ll * f0.w + lh * f1.w + hl * f2.w + hh * f3.w);
    *(float2*)&out[ob]        = r0;
    *(float2*)&out[ob + RESV] = r1;
}

// ---------------- launch ----------------------------------------------------
extern "C" void kernel_launch(void* const* d_in, const int* in_sizes, int n_in,
                              void* d_out, int out_size) {
    const float* x    = (const float*)d_in[0];
    const float* wtf  = (const float*)d_in[1];
    const float* iwtf = (const float*)d_in[2];
    const float* dww  = (const float*)d_in[3];
    const float* dwb  = (const float*)d_in[4];
    const float* pw   = (const float*)d_in[5];
    const float* pb   = (const float*)d_in[6];
    const float* ab   = (const float*)d_in[7];
    const int*   bidx = (const int*)d_in[8];
    float* out = (float*)d_out;

    bias_kernel<<<128, 256>>>(ab, bidx);
    wt_kernel<<<dim3(128, 512), 128>>>(x, wtf);
    attn_mat_kernel<<<4096, 256>>>(dww, dwb);
    attn_av_kernel<<<512, 256>>>();
    proj_gemm<<<dim3(256, 4), 256>>>(pw, pb);
    iwt_kernel<<<dim3(128, 512), 128>>>(iwtf, out);
}

// round 7
// speedup vs baseline: 1.2384x; 1.0270x over previous
#include <cuda_runtime.h>

#define DIMC 256
#define RESV 256
#define H2 128
#define HEADS 8
#define HD 32
#define NPIX 64
#define NWIN 512
#define PIXTOT (NWIN * NPIX)   // 32768
#define ATTN_SCALE 0.17677669529663687f
#define SROW 68                // padded smem row stride (floats)
#define PSROW 132              // proj smem row stride (floats), 128-wide tiles

// ---------------- scratch (static device allocations; no cudaMalloc) -------
__device__ float g_ll[2 * DIMC * H2 * H2];
__device__ float g_lh[2 * DIMC * H2 * H2];
__device__ float g_hl[2 * DIMC * H2 * H2];
__device__ float g_hh[2 * DIMC * H2 * H2];
__device__ float g_attn[NWIN * HEADS * NPIX * NPIX]; // softmax'd attn, [wh][m][n]
__device__ float g_att[DIMC * PIXTOT];    // relu(attention out), [c][pix]
__device__ float g_proj[DIMC * PIXTOT];   // proj out, [o][pix]
__device__ float g_bias[HEADS * NPIX * NPIX];

// ---------------- K0: expand attention bias table ---------------------------
__global__ void bias_kernel(const float* __restrict__ ab, const int* __restrict__ bidx) {
    int i = blockIdx.x * 256 + threadIdx.x;     // 32768 total
    int h = i >> 12;
    g_bias[i] = ab[h * 64 + bidx[i & 4095]];
}

// ---------------- K1: wavelet transform (depthwise 2x2 stride 2) -----------
__global__ void wt_kernel(const float* __restrict__ x, const float* __restrict__ wt) {
    int xo = threadIdx.x;          // 0..127
    int y  = blockIdx.x;           // 0..127
    int bc = blockIdx.y;           // 0..511 (b*256 + c)
    int c  = bc & 255;

    const float4 f0 = __ldg((const float4*)&wt[(4 * c + 0) * 4]);
    const float4 f1 = __ldg((const float4*)&wt[(4 * c + 1) * 4]);
    const float4 f2 = __ldg((const float4*)&wt[(4 * c + 2) * 4]);
    const float4 f3 = __ldg((const float4*)&wt[(4 * c + 3) * 4]);

    int ib = (bc * RESV + 2 * y) * RESV + 2 * xo;
    float2 p0 = *(const float2*)&x[ib];
    float2 p1 = *(const float2*)&x[ib + RESV];

    int ob = (bc * H2 + y) * H2 + xo;
    g_ll[ob] = p0.x * f0.x + p0.y * f0.y + p1.x * f0.z + p1.y * f0.w;
    g_lh[ob] = p0.x * f1.x + p0.y * f1.y + p1.x * f1.z + p1.y * f1.w;
    g_hl[ob] = p0.x * f2.x + p0.y * f2.y + p1.x * f2.z + p1.y * f2.w;
    g_hh[ob] = p0.x * f3.x + p0.y * f3.y + p1.x * f3.z + p1.y * f3.w;
}

// ---------------- K2a: attention matrices (all heads parallel) --------------
// One CTA per (window, head): q = dwconv5x5(lh), attn = softmax(qk*scale+bias)
// Output stored TRANSPOSED: g_attn[wh][m][n]
__global__ __launch_bounds__(256) void attn_mat_kernel(
    const float* __restrict__ dww, const float* __restrict__ dwb) {
    __shared__ float lh_s[HD * SROW];
    __shared__ float k_s[HD * SROW];
    __shared__ float q_s[HD * SROW];
    __shared__ float w_s[HD * 25];

    const int t  = threadIdx.x;
    const int wh = blockIdx.x;           // 0..4095
    const int w  = wh >> 3;
    const int h  = wh & 7;
    const int b  = w >> 8;
    const int wy = (w >> 4) & 15;
    const int wx = w & 15;
    const int dl = t >> 3;               // 0..31
    const int py = t & 7;                // 0..7

    // ---- load lh / hl window slices ----
    {
        int ch   = b * DIMC + h * HD + dl;
        int base = (ch * H2 + wy * 8 + py) * H2 + wx * 8;
        int o0   = dl * SROW + py * 8;
        *(float4*)&lh_s[o0]     = *(const float4*)&g_lh[base];
        *(float4*)&lh_s[o0 + 4] = *(const float4*)&g_lh[base + 4];
        *(float4*)&k_s[o0]      = *(const float4*)&g_hl[base];
        *(float4*)&k_s[o0 + 4]  = *(const float4*)&g_hl[base + 4];
    }
    for (int i = t; i < HD * 25; i += 256) w_s[i] = dww[h * HD * 25 + i];
    __syncthreads();

    // ---- q = depthwise 5x5 conv on lh (zero pad, per-window) ----
    // register row-hoist: 2x LDS.128 per active row, all x-bounds compile-time
    {
        float accq[8];
        float bias0 = __ldg(&dwb[h * HD + dl]);
        #pragma unroll
        for (int px = 0; px < 8; ++px) accq[px] = bias0;
        #pragma unroll
        for (int u = 0; u < 5; ++u) {
            int yy = py + u - 2;
            if (yy >= 0 && yy < 8) {
                float4 r0 = *(const float4*)&lh_s[dl * SROW + yy * 8];
                float4 r1 = *(const float4*)&lh_s[dl * SROW + yy * 8 + 4];
                float r[8] = {r0.x, r0.y, r0.z, r0.w, r1.x, r1.y, r1.z, r1.w};
                #pragma unroll
                for (int v = 0; v < 5; ++v) {
                    float wv = w_s[dl * 25 + u * 5 + v];
                    #pragma unroll
                    for (int px = 0; px < 8; ++px) {
                        int xx = px + v - 2;
                        if (xx >= 0 && xx < 8)
                            accq[px] += r[xx] * wv;
                    }
                }
            }
        }
        #pragma unroll
        for (int px = 0; px < 8; ++px) q_s[dl * SROW + py * 8 + px] = accq[px];
    }
    __syncthreads();

    // ---- attn[n][m] = softmax_m(q.k * scale + bias) -> global (transposed) ----
    {
        int n  = t >> 2;             // 0..63
        int mq = t & 3;              // 16 m's each
        float acc[16];
        #pragma unroll
        for (int i = 0; i < 16; ++i) acc[i] = 0.f;

        #pragma unroll 4
        for (int d2 = 0; d2 < HD; ++d2) {
            float qd = q_s[d2 * SROW + n];
            const float* kp = &k_s[d2 * SROW + mq * 16];
            float4 k0 = *(const float4*)(kp);
            float4 k1 = *(const float4*)(kp + 4);
            float4 k2 = *(const float4*)(kp + 8);
            float4 k3 = *(const float4*)(kp + 12);
            acc[0]  += qd * k0.x;  acc[1]  += qd * k0.y;
            acc[2]  += qd * k0.z;  acc[3]  += qd * k0.w;
            acc[4]  += qd * k1.x;  acc[5]  += qd * k1.y;
            acc[6]  += qd * k1.z;  acc[7]  += qd * k1.w;
            acc[8]  += qd * k2.x;  acc[9]  += qd * k2.y;
            acc[10] += qd * k2.z;  acc[11] += qd * k2.w;
            acc[12] += qd * k3.x;  acc[13] += qd * k3.y;
            acc[14] += qd * k3.z;  acc[15] += qd * k3.w;
        }

        const float* bptr = &g_bias[h * 4096 + n * 64 + mq * 16];
        float mx = -1e30f;
        #pragma unroll
        for (int mi = 0; mi < 16; ++mi) {
            acc[mi] = acc[mi] * ATTN_SCALE + __ldg(&bptr[mi]);
            mx = fmaxf(mx, acc[mi]);
        }
        mx = fmaxf(mx, __shfl_xor_sync(0xffffffffu, mx, 1));
        mx = fmaxf(mx, __shfl_xor_sync(0xffffffffu, mx, 2));
        float s = 0.f;
        #pragma unroll
        for (int mi = 0; mi < 16; ++mi) {
            float e = __expf(acc[mi] - mx);
            acc[mi] = e;
            s += e;
        }
        s += __shfl_xor_sync(0xffffffffu, s, 1);
        s += __shfl_xor_sync(0xffffffffu, s, 2);
        float inv = 1.f / s;

        float* op = &g_attn[wh * 4096];
        #pragma unroll
        for (int mi = 0; mi < 16; ++mi)
            op[(mq * 16 + mi) * 64 + n] = acc[mi] * inv;   // [m][n]
    }
}

// ---------------- K2b: sequential AV chain per window -----------------------
__global__ __launch_bounds__(256) void attn_av_kernel() {
    __shared__ float v_s[HD * NPIX];        // 8KB
    __shared__ float o_s[HD * NPIX];        // 8KB
    __shared__ float attn_s[NPIX * NPIX];   // 16KB

    const int t  = threadIdx.x;
    const int w  = blockIdx.x;
    const int b  = w >> 8;
    const int wy = (w >> 4) & 15;
    const int wx = w & 15;
    const int wp   = t >> 5;             // warp 0..7 -> d rows 4wp..4wp+3
    const int lane = t & 31;             // n and n+32

    float4 pa[4];   // prefetched attn chunk
    float4 pl[2];   // prefetched ll chunk

    {
        const float* ap = &g_attn[(w * 8 + 0) * 4096];
        #pragma unroll
        for (int i = 0; i < 4; ++i)
            pa[i] = *(const float4*)&ap[(t + 256 * i) * 4];
        #pragma unroll
        for (int i = 0; i < 2; ++i) {
            int c  = t + 256 * i;
            int d  = c >> 4;
            int m0 = (c & 15) * 4;
            int ch = b * DIMC + 0 * HD + d;
            pl[i] = *(const float4*)&g_ll[(ch * H2 + wy * 8 + (m0 >> 3)) * H2
                                          + wx * 8 + (m0 & 7)];
        }
    }

    for (int h = 0; h < HEADS; ++h) {
        __syncthreads();

        #pragma unroll
        for (int i = 0; i < 4; ++i)
            *(float4*)&attn_s[(t + 256 * i) * 4] = pa[i];
        #pragma unroll
        for (int i = 0; i < 2; ++i) {
            int c = t + 256 * i;
            float4 v4 = pl[i];
            if (h > 0) {
                float4 o4 = *(const float4*)&o_s[c * 4];
                v4.x += o4.x; v4.y += o4.y; v4.z += o4.z; v4.w += o4.w;
                int d  = c >> 4;
                int m0 = (c & 15) * 4;
                float4 r = make_float4(fmaxf(o4.x, 0.f), fmaxf(o4.y, 0.f),
                                       fmaxf(o4.z, 0.f), fmaxf(o4.w, 0.f));
                *(float4*)&g_att[((h - 1) * HD + d) * PIXTOT + w * 64 + m0] = r;
            }
            *(float4*)&v_s[c * 4] = v4;
        }

        if (h < HEADS - 1) {
            const float* ap = &g_attn[(w * 8 + h + 1) * 4096];
            #pragma unroll
            for (int i = 0; i < 4; ++i)
                pa[i] = *(const float4*)&ap[(t + 256 * i) * 4];
            #pragma unroll
            for (int i = 0; i < 2; ++i) {
                int c  = t + 256 * i;
                int d  = c >> 4;
                int m0 = (c & 15) * 4;
                int ch = b * DIMC + (h + 1) * HD + d;
                pl[i] = *(const float4*)&g_ll[(ch * H2 + wy * 8 + (m0 >> 3)) * H2
                                              + wx * 8 + (m0 & 7)];
            }
        }
        __syncthreads();

        float acc[4][2];
        #pragma unroll
        for (int j = 0; j < 4; ++j) { acc[j][0] = 0.f; acc[j][1] = 0.f; }

        #pragma unroll
        for (int m = 0; m < 64; m += 4) {
            float4 a0 = *(const float4*)&v_s[(4 * wp + 0) * 64 + m];
            float4 a1 = *(const float4*)&v_s[(4 * wp + 1) * 64 + m];
            float4 a2 = *(const float4*)&v_s[(4 * wp + 2) * 64 + m];
            float4 a3 = *(const float4*)&v_s[(4 * wp + 3) * 64 + m];
            float b0l = attn_s[(m + 0) * 64 + lane];
            float b1l = attn_s[(m + 1) * 64 + lane];
            float b2l = attn_s[(m + 2) * 64 + lane];
            float b3l = attn_s[(m + 3) * 64 + lane];
            float b0h = attn_s[(m + 0) * 64 + lane + 32];
            float b1h = attn_s[(m + 1) * 64 + lane + 32];
            float b2h = attn_s[(m + 2) * 64 + lane + 32];
            float b3h = attn_s[(m + 3) * 64 + lane + 32];
            acc[0][0] += a0.x * b0l + a0.y * b1l + a0.z * b2l + a0.w * b3l;
            acc[1][0] += a1.x * b0l + a1.y * b1l + a1.z * b2l + a1.w * b3l;
            acc[2][0] += a2.x * b0l + a2.y * b1l + a2.z * b2l + a2.w * b3l;
            acc[3][0] += a3.x * b0l + a3.y * b1l + a3.z * b2l + a3.w * b3l;
            acc[0][1] += a0.x * b0h + a0.y * b1h + a0.z * b2h + a0.w * b3h;
            acc[1][1] += a1.x * b0h + a1.y * b1h + a1.z * b2h + a1.w * b3h;
            acc[2][1] += a2.x * b0h + a2.y * b1h + a2.z * b2h + a2.w * b3h;
            acc[3][1] += a3.x * b0h + a3.y * b1h + a3.z * b2h + a3.w * b3h;
        }
        #pragma unroll
        for (int j = 0; j < 4; ++j) {
            o_s[(4 * wp + j) * 64 + lane]      = acc[j][0];
            o_s[(4 * wp + j) * 64 + lane + 32] = acc[j][1];
        }
    }

    __syncthreads();
    #pragma unroll
    for (int i = 0; i < 2; ++i) {
        int c  = t + 256 * i;
        int d  = c >> 4;
        int m0 = (c & 15) * 4;
        float4 o4 = *(const float4*)&o_s[c * 4];
        float4 r = make_float4(fmaxf(o4.x, 0.f), fmaxf(o4.y, 0.f),
                               fmaxf(o4.z, 0.f), fmaxf(o4.w, 0.f));
        *(float4*)&g_att[(7 * HD + d) * PIXTOT + w * 64 + m0] = r;
    }
}

// ---------------- K3: proj GEMM  C[256,32768] = W[256,256] @ A + bias ------
// 128x128 tile, 8x8 per-thread micro-tile, register-prefetch pipeline
__global__ __launch_bounds__(256) void proj_gemm(
    const float* __restrict__ Wm, const float* __restrict__ pb) {
    __shared__ float As[16 * PSROW];   // As[k][m], m-tile 128
    __shared__ float Bs[16 * PSROW];   // Bs[k][n], n-tile 128

    const int t  = threadIdx.x;
    const int n0 = blockIdx.x * 128;   // 256 tiles
    const int m0 = blockIdx.y * 128;   // 2 tiles
    const int tx = t & 15, ty = t >> 4;

    // load mapping
    const int am = t >> 1;             // 0..127
    const int ak = (t & 1) * 8;        // 0 or 8
    const int bk = t >> 4;             // 0..15
    const int bn = (t & 15) * 8;       // 0..120

    float acc[8][8];
    #pragma unroll
    for (int i = 0; i < 8; ++i)
        #pragma unroll
        for (int j = 0; j < 8; ++j) acc[i][j] = 0.f;

    // prefetch k-tile 0
    float4 pa0 = *(const float4*)&Wm[(m0 + am) * 256 + ak];
    float4 pa1 = *(const float4*)&Wm[(m0 + am) * 256 + ak + 4];
    float4 pb0 = *(const float4*)&g_att[bk * PIXTOT + n0 + bn];
    float4 pb1 = *(const float4*)&g_att[bk * PIXTOT + n0 + bn + 4];

    for (int k0 = 0; k0 < 256; k0 += 16) {
        // commit prefetched tile to smem (A transposed to [k][m])
        As[(ak + 0) * PSROW + am] = pa0.x;
        As[(ak + 1) * PSROW + am] = pa0.y;
        As[(ak + 2) * PSROW + am] = pa0.z;
        As[(ak + 3) * PSROW + am] = pa0.w;
        As[(ak + 4) * PSROW + am] = pa1.x;
        As[(ak + 5) * PSROW + am] = pa1.y;
        As[(ak + 6) * PSROW + am] = pa1.z;
        As[(ak + 7) * PSROW + am] = pa1.w;
        *(float4*)&Bs[bk * PSROW + bn]     = pb0;
        *(float4*)&Bs[bk * PSROW + bn + 4] = pb1;
        __syncthreads();

        // prefetch next k-tile while FMAs run
        if (k0 < 240) {
            pa0 = *(const float4*)&Wm[(m0 + am) * 256 + k0 + 16 + ak];
            pa1 = *(const float4*)&Wm[(m0 + am) * 256 + k0 + 16 + ak + 4];
            pb0 = *(const float4*)&g_att[(k0 + 16 + bk) * PIXTOT + n0 + bn];
            pb1 = *(const float4*)&g_att[(k0 + 16 + bk) * PIXTOT + n0 + bn + 4];
        }

        #pragma unroll
        for (int k = 0; k < 16; ++k) {
            float4 a0 = *(const float4*)&As[k * PSROW + ty * 4];
            float4 a1 = *(const float4*)&As[k * PSROW + 64 + ty * 4];
            float4 b0 = *(const float4*)&Bs[k * PSROW + tx * 4];
            float4 b1 = *(const float4*)&Bs[k * PSROW + 64 + tx * 4];
            float av[8] = {a0.x, a0.y, a0.z, a0.w, a1.x, a1.y, a1.z, a1.w};
            float bv[8] = {b0.x, b0.y, b0.z, b0.w, b1.x, b1.y, b1.z, b1.w};
            #pragma unroll
            for (int i = 0; i < 8; ++i)
                #pragma unroll
                for (int j = 0; j < 8; ++j)
                    acc[i][j] += av[i] * bv[j];
        }
        __syncthreads();
    }

    #pragma unroll
    for (int i = 0; i < 8; ++i) {
        int m = m0 + ((i < 4) ? (ty * 4 + i) : (64 + ty * 4 + i - 4));
        float bias = __ldg(&pb[m]);
        float* rp = &g_proj[m * PIXTOT + n0];
        float4 r0 = make_float4(acc[i][0] + bias, acc[i][1] + bias,
                                acc[i][2] + bias, acc[i][3] + bias);
        float4 r1 = make_float4(acc[i][4] + bias, acc[i][5] + bias,
                                acc[i][6] + bias, acc[i][7] + bias);
        *(float4*)&rp[tx * 4]      = r0;
        *(float4*)&rp[64 + tx * 4] = r1;
    }
}

// ---------------- K4: inverse wavelet (transposed depthwise 2x2) ------------
__global__ void iwt_kernel(const float* __restrict__ iwt, float* __restrict__ out) {
    int xo = threadIdx.x;          // 0..127
    int y  = blockIdx.x;           // 0..127
    int bc = blockIdx.y;           // 0..511
    int b  = bc >> 8, c = bc & 255;

    int base = (bc * H2 + y) * H2 + xo;
    float lh = g_lh[base], hl = g_hl[base], hh = g_hh[base];

    int wy = y >> 3, pyy = y & 7, wx = xo >> 3, pxx = xo & 7;
    int wdx = (b * 16 + wy) * 16 + wx;
    float ll = g_proj[c * PIXTOT + wdx * 64 + pyy * 8 + pxx];

    const float4 f0 = __ldg((const float4*)&iwt[(4 * c + 0) * 4]);
    const float4 f1 = __ldg((const float4*)&iwt[(4 * c + 1) * 4]);
    const float4 f2 = __ldg((const float4*)&iwt[(4 * c + 2) * 4]);
    const float4 f3 = __ldg((const float4*)&iwt[(4 * c + 3) * 4]);

    int ob = (bc * RESV + 2 * y) * RESV + 2 * xo;
    float2 r0 = make_float2(ll * f0.x + lh * f1.x + hl * f2.x + hh * f3.x,
                            ll * f0.y + lh * f1.y + hl * f2.y + hh * f3.y);
    float2 r1 = make_float2(ll * f0.z + lh * f1.z + hl * f2.z + hh * f3.z,
                            ll * f0.w + lh * f1.w + hl * f2.w + hh * f3.w);
    *(float2*)&out[ob]        = r0;
    *(float2*)&out[ob + RESV] = r1;
}

// ---------------- launch ----------------------------------------------------
extern "C" void kernel_launch(void* const* d_in, const int* in_sizes, int n_in,
                              void* d_out, int out_size) {
    const float* x    = (const float*)d_in[0];
    const float* wtf  = (const float*)d_in[1];
    const float* iwtf = (const float*)d_in[2];
    const float* dww  = (const float*)d_in[3];
    const float* dwb  = (const float*)d_in[4];
    const float* pw   = (const float*)d_in[5];
    const float* pb   = (const float*)d_in[6];
    const float* ab   = (const float*)d_in[7];
    const int*   bidx = (const int*)d_in[8];
    float* out = (float*)d_out;

    bias_kernel<<<128, 256>>>(ab, bidx);
    wt_kernel<<<dim3(128, 512), 128>>>(x, wtf);
    attn_mat_kernel<<<4096, 256>>>(dww, dwb);
    attn_av_kernel<<<512, 256>>>();
    proj_gemm<<<dim3(256, 2), 256>>>(pw, pb);
    iwt_kernel<<<dim3(128, 512), 128>>>(iwtf, out);
}

// round 8
// speedup vs baseline: 1.2930x; 1.0441x over previous
#include <cuda_runtime.h>

#define DIMC 256
#define RESV 256
#define H2 128
#define HEADS 8
#define HD 32
#define NPIX 64
#define NWIN 512
#define PIXTOT (NWIN * NPIX)   // 32768
#define ATTN_SCALE 0.17677669529663687f
#define SROW 68                // padded smem row stride (floats)
#define PSROW 132              // proj smem row stride (floats), 128-wide tiles

typedef unsigned long long ull;

// ---- packed fp32x2 helpers (FFMA2 — only reachable via PTX fma.rn.f32x2) ----
__device__ __forceinline__ void ffma2(ull& d, ull a, ull b) {
    asm("fma.rn.f32x2 %0, %1, %2, %0;" : "+l"(d) : "l"(a), "l"(b));
}
__device__ __forceinline__ ull pack2(float lo, float hi) {
    ull r; asm("mov.b64 %0, {%1, %2};" : "=l"(r) : "f"(lo), "f"(hi)); return r;
}
__device__ __forceinline__ float2 unpack2(ull v) {
    float2 r; asm("mov.b64 {%0, %1}, %2;" : "=f"(r.x), "=f"(r.y) : "l"(v)); return r;
}

// ---------------- scratch (static device allocations; no cudaMalloc) -------
__device__ float g_ll[2 * DIMC * H2 * H2];
__device__ float g_lh[2 * DIMC * H2 * H2];
__device__ float g_hl[2 * DIMC * H2 * H2];
__device__ float g_hh[2 * DIMC * H2 * H2];
__device__ float g_attn[NWIN * HEADS * NPIX * NPIX]; // softmax'd attn, [wh][m][n]
__device__ float g_att[DIMC * PIXTOT];    // relu(attention out), [c][pix]
__device__ float g_proj[DIMC * PIXTOT];   // proj out, [o][pix]
__device__ float g_bias[HEADS * NPIX * NPIX];

// ---------------- K0: expand attention bias table ---------------------------
__global__ void bias_kernel(const float* __restrict__ ab, const int* __restrict__ bidx) {
    int i = blockIdx.x * 256 + threadIdx.x;     // 32768 total
    int h = i >> 12;
    g_bias[i] = ab[h * 64 + bidx[i & 4095]];
}

// ---------------- K1: wavelet transform (depthwise 2x2 stride 2) -----------
__global__ void wt_kernel(const float* __restrict__ x, const float* __restrict__ wt) {
    int xo = threadIdx.x;          // 0..127
    int y  = blockIdx.x;           // 0..127
    int bc = blockIdx.y;           // 0..511 (b*256 + c)
    int c  = bc & 255;

    const float4 f0 = __ldg((const float4*)&wt[(4 * c + 0) * 4]);
    const float4 f1 = __ldg((const float4*)&wt[(4 * c + 1) * 4]);
    const float4 f2 = __ldg((const float4*)&wt[(4 * c + 2) * 4]);
    const float4 f3 = __ldg((const float4*)&wt[(4 * c + 3) * 4]);

    int ib = (bc * RESV + 2 * y) * RESV + 2 * xo;
    float2 p0 = *(const float2*)&x[ib];
    float2 p1 = *(const float2*)&x[ib + RESV];

    int ob = (bc * H2 + y) * H2 + xo;
    g_ll[ob] = p0.x * f0.x + p0.y * f0.y + p1.x * f0.z + p1.y * f0.w;
    g_lh[ob] = p0.x * f1.x + p0.y * f1.y + p1.x * f1.z + p1.y * f1.w;
    g_hl[ob] = p0.x * f2.x + p0.y * f2.y + p1.x * f2.z + p1.y * f2.w;
    g_hh[ob] = p0.x * f3.x + p0.y * f3.y + p1.x * f3.z + p1.y * f3.w;
}

// ---------------- K2a: attention matrices (all heads parallel) --------------
// One CTA per (window, head): q = dwconv5x5(lh), attn = softmax(qk*scale+bias)
// Output stored TRANSPOSED: g_attn[wh][m][n]
__global__ __launch_bounds__(256) void attn_mat_kernel(
    const float* __restrict__ dww, const float* __restrict__ dwb) {
    __shared__ float lh_s[HD * SROW];
    __shared__ float k_s[HD * SROW];
    __shared__ float q_s[HD * SROW];
    __shared__ float w_s[HD * 25];

    const int t  = threadIdx.x;
    const int wh = blockIdx.x;           // 0..4095
    const int w  = wh >> 3;
    const int h  = wh & 7;
    const int b  = w >> 8;
    const int wy = (w >> 4) & 15;
    const int wx = w & 15;
    const int dl = t >> 3;               // 0..31
    const int py = t & 7;                // 0..7

    // ---- load lh / hl window slices ----
    {
        int ch   = b * DIMC + h * HD + dl;
        int base = (ch * H2 + wy * 8 + py) * H2 + wx * 8;
        int o0   = dl * SROW + py * 8;
        *(float4*)&lh_s[o0]     = *(const float4*)&g_lh[base];
        *(float4*)&lh_s[o0 + 4] = *(const float4*)&g_lh[base + 4];
        *(float4*)&k_s[o0]      = *(const float4*)&g_hl[base];
        *(float4*)&k_s[o0 + 4]  = *(const float4*)&g_hl[base + 4];
    }
    for (int i = t; i < HD * 25; i += 256) w_s[i] = dww[h * HD * 25 + i];
    __syncthreads();

    // ---- q = depthwise 5x5 conv on lh (zero pad, per-window) ----
    {
        float accq[8];
        float bias0 = __ldg(&dwb[h * HD + dl]);
        #pragma unroll
        for (int px = 0; px < 8; ++px) accq[px] = bias0;
        #pragma unroll
        for (int u = 0; u < 5; ++u) {
            int yy = py + u - 2;
            if (yy >= 0 && yy < 8) {
                float4 r0 = *(const float4*)&lh_s[dl * SROW + yy * 8];
                float4 r1 = *(const float4*)&lh_s[dl * SROW + yy * 8 + 4];
                float r[8] = {r0.x, r0.y, r0.z, r0.w, r1.x, r1.y, r1.z, r1.w};
                #pragma unroll
                for (int v = 0; v < 5; ++v) {
                    float wv = w_s[dl * 25 + u * 5 + v];
                    #pragma unroll
                    for (int px = 0; px < 8; ++px) {
                        int xx = px + v - 2;
                        if (xx >= 0 && xx < 8)
                            accq[px] += r[xx] * wv;
                    }
                }
            }
        }
        #pragma unroll
        for (int px = 0; px < 8; ++px) q_s[dl * SROW + py * 8 + px] = accq[px];
    }
    __syncthreads();

    // ---- attn[n][m] = softmax_m(q.k * scale + bias) -> global (transposed) ----
    // QK inner product in packed f32x2 (pairs along m)
    {
        int n  = t >> 2;             // 0..63
        int mq = t & 3;              // 16 m's each
        ull acc2[8];
        #pragma unroll
        for (int i = 0; i < 8; ++i) acc2[i] = 0ull;

        #pragma unroll 4
        for (int d2 = 0; d2 < HD; ++d2) {
            float qd = q_s[d2 * SROW + n];
            ull pq = pack2(qd, qd);
            const float* kp = &k_s[d2 * SROW + mq * 16];
            ulonglong2 k01 = *(const ulonglong2*)(kp);       // m pairs (0,1),(2,3)
            ulonglong2 k23 = *(const ulonglong2*)(kp + 4);   // (4,5),(6,7)
            ulonglong2 k45 = *(const ulonglong2*)(kp + 8);
            ulonglong2 k67 = *(const ulonglong2*)(kp + 12);
            ffma2(acc2[0], pq, k01.x);
            ffma2(acc2[1], pq, k01.y);
            ffma2(acc2[2], pq, k23.x);
            ffma2(acc2[3], pq, k23.y);
            ffma2(acc2[4], pq, k45.x);
            ffma2(acc2[5], pq, k45.y);
            ffma2(acc2[6], pq, k67.x);
            ffma2(acc2[7], pq, k67.y);
        }

        float acc[16];
        #pragma unroll
        for (int i = 0; i < 8; ++i) {
            float2 u = unpack2(acc2[i]);
            acc[2 * i]     = u.x;
            acc[2 * i + 1] = u.y;
        }

        const float* bptr = &g_bias[h * 4096 + n * 64 + mq * 16];
        float mx = -1e30f;
        #pragma unroll
        for (int mi = 0; mi < 16; ++mi) {
            acc[mi] = acc[mi] * ATTN_SCALE + __ldg(&bptr[mi]);
            mx = fmaxf(mx, acc[mi]);
        }
        mx = fmaxf(mx, __shfl_xor_sync(0xffffffffu, mx, 1));
        mx = fmaxf(mx, __shfl_xor_sync(0xffffffffu, mx, 2));
        float s = 0.f;
        #pragma unroll
        for (int mi = 0; mi < 16; ++mi) {
            float e = __expf(acc[mi] - mx);
            acc[mi] = e;
            s += e;
        }
        s += __shfl_xor_sync(0xffffffffu, s, 1);
        s += __shfl_xor_sync(0xffffffffu, s, 2);
        float inv = 1.f / s;

        float* op = &g_attn[wh * 4096];
        #pragma unroll
        for (int mi = 0; mi < 16; ++mi)
            op[(mq * 16 + mi) * 64 + n] = acc[mi] * inv;   // [m][n]
    }
}

// ---------------- K2b: sequential AV chain per window -----------------------
__global__ __launch_bounds__(256) void attn_av_kernel() {
    __shared__ float v_s[HD * NPIX];        // 8KB
    __shared__ float o_s[HD * NPIX];        // 8KB
    __shared__ float attn_s[NPIX * NPIX];   // 16KB

    const int t  = threadIdx.x;
    const int w  = blockIdx.x;
    const int b  = w >> 8;
    const int wy = (w >> 4) & 15;
    const int wx = w & 15;
    const int wp   = t >> 5;             // warp 0..7 -> d rows 4wp..4wp+3
    const int lane = t & 31;             // n and n+32

    float4 pa[4];   // prefetched attn chunk
    float4 pl[2];   // prefetched ll chunk

    {
        const float* ap = &g_attn[(w * 8 + 0) * 4096];
        #pragma unroll
        for (int i = 0; i < 4; ++i)
            pa[i] = *(const float4*)&ap[(t + 256 * i) * 4];
        #pragma unroll
        for (int i = 0; i < 2; ++i) {
            int c  = t + 256 * i;
            int d  = c >> 4;
            int m0 = (c & 15) * 4;
            int ch = b * DIMC + 0 * HD + d;
            pl[i] = *(const float4*)&g_ll[(ch * H2 + wy * 8 + (m0 >> 3)) * H2
                                          + wx * 8 + (m0 & 7)];
        }
    }

    for (int h = 0; h < HEADS; ++h) {
        __syncthreads();

        #pragma unroll
        for (int i = 0; i < 4; ++i)
            *(float4*)&attn_s[(t + 256 * i) * 4] = pa[i];
        #pragma unroll
        for (int i = 0; i < 2; ++i) {
            int c = t + 256 * i;
            float4 v4 = pl[i];
            if (h > 0) {
                float4 o4 = *(const float4*)&o_s[c * 4];
                v4.x += o4.x; v4.y += o4.y; v4.z += o4.z; v4.w += o4.w;
                int d  = c >> 4;
                int m0 = (c & 15) * 4;
                float4 r = make_float4(fmaxf(o4.x, 0.f), fmaxf(o4.y, 0.f),
                                       fmaxf(o4.z, 0.f), fmaxf(o4.w, 0.f));
                *(float4*)&g_att[((h - 1) * HD + d) * PIXTOT + w * 64 + m0] = r;
            }
            *(float4*)&v_s[c * 4] = v4;
        }

        if (h < HEADS - 1) {
            const float* ap = &g_attn[(w * 8 + h + 1) * 4096];
            #pragma unroll
            for (int i = 0; i < 4; ++i)
                pa[i] = *(const float4*)&ap[(t + 256 * i) * 4];
            #pragma unroll
            for (int i = 0; i < 2; ++i) {
                int c  = t + 256 * i;
                int d  = c >> 4;
                int m0 = (c & 15) * 4;
                int ch = b * DIMC + (h + 1) * HD + d;
                pl[i] = *(const float4*)&g_ll[(ch * H2 + wy * 8 + (m0 >> 3)) * H2
                                              + wx * 8 + (m0 & 7)];
            }
        }
        __syncthreads();

        // ---- out[d][n] = sum_m v[d][m] * attn_t[m][n], packed pairs along m ----
        ull acc2[4][2];
        #pragma unroll
        for (int j = 0; j < 4; ++j) { acc2[j][0] = 0ull; acc2[j][1] = 0ull; }

        #pragma unroll
        for (int m = 0; m < 64; m += 4) {
            ulonglong2 va0 = *(const ulonglong2*)&v_s[(4 * wp + 0) * 64 + m];
            ulonglong2 va1 = *(const ulonglong2*)&v_s[(4 * wp + 1) * 64 + m];
            ulonglong2 va2 = *(const ulonglong2*)&v_s[(4 * wp + 2) * 64 + m];
            ulonglong2 va3 = *(const ulonglong2*)&v_s[(4 * wp + 3) * 64 + m];
            float b0l = attn_s[(m + 0) * 64 + lane];
            float b1l = attn_s[(m + 1) * 64 + lane];
            float b2l = attn_s[(m + 2) * 64 + lane];
            float b3l = attn_s[(m + 3) * 64 + lane];
            float b0h = attn_s[(m + 0) * 64 + lane + 32];
            float b1h = attn_s[(m + 1) * 64 + lane + 32];
            float b2h = attn_s[(m + 2) * 64 + lane + 32];
            float b3h = attn_s[(m + 3) * 64 + lane + 32];
            ull bl01 = pack2(b0l, b1l), bl23 = pack2(b2l, b3l);
            ull bh01 = pack2(b0h, b1h), bh23 = pack2(b2h, b3h);
            ffma2(acc2[0][0], va0.x, bl01); ffma2(acc2[0][0], va0.y, bl23);
            ffma2(acc2[1][0], va1.x, bl01); ffma2(acc2[1][0], va1.y, bl23);
            ffma2(acc2[2][0], va2.x, bl01); ffma2(acc2[2][0], va2.y, bl23);
            ffma2(acc2[3][0], va3.x, bl01); ffma2(acc2[3][0], va3.y, bl23);
            ffma2(acc2[0][1], va0.x, bh01); ffma2(acc2[0][1], va0.y, bh23);
            ffma2(acc2[1][1], va1.x, bh01); ffma2(acc2[1][1], va1.y, bh23);
            ffma2(acc2[2][1], va2.x, bh01); ffma2(acc2[2][1], va2.y, bh23);
            ffma2(acc2[3][1], va3.x, bh01); ffma2(acc2[3][1], va3.y, bh23);
        }
        #pragma unroll
        for (int j = 0; j < 4; ++j) {
            float2 u0 = unpack2(acc2[j][0]);
            float2 u1 = unpack2(acc2[j][1]);
            o_s[(4 * wp + j) * 64 + lane]      = u0.x + u0.y;
            o_s[(4 * wp + j) * 64 + lane + 32] = u1.x + u1.y;
        }
    }

    __syncthreads();
    #pragma unroll
    for (int i = 0; i < 2; ++i) {
        int c  = t + 256 * i;
        int d  = c >> 4;
        int m0 = (c & 15) * 4;
        float4 o4 = *(const float4*)&o_s[c * 4];
        float4 r = make_float4(fmaxf(o4.x, 0.f), fmaxf(o4.y, 0.f),
                               fmaxf(o4.z, 0.f), fmaxf(o4.w, 0.f));
        *(float4*)&g_att[(7 * HD + d) * PIXTOT + w * 64 + m0] = r;
    }
}

// ---------------- K3: proj GEMM  C[256,32768] = W[256,256] @ A + bias ------
// 128x128 tile, 8x8 per-thread micro-tile (packed f32x2 along n),
// register-prefetch pipeline
__global__ __launch_bounds__(256) void proj_gemm(
    const float* __restrict__ Wm, const float* __restrict__ pb) {
    __shared__ float As[16 * PSROW];   // As[k][m], m-tile 128
    __shared__ float Bs[16 * PSROW];   // Bs[k][n], n-tile 128

    const int t  = threadIdx.x;
    const int n0 = blockIdx.x * 128;   // 256 tiles
    const int m0 = blockIdx.y * 128;   // 2 tiles
    const int tx = t & 15, ty = t >> 4;

    // load mapping
    const int am = t >> 1;             // 0..127
    const int ak = (t & 1) * 8;        // 0 or 8
    const int bk = t >> 4;             // 0..15
    const int bn = (t & 15) * 8;       // 0..120

    ull acc2[8][4];                    // [mi][n-pair]: pairs (0,1)(2,3)(64,65)(66,67)+tx*4
    #pragma unroll
    for (int i = 0; i < 8; ++i)
        #pragma unroll
        for (int j = 0; j < 4; ++j) acc2[i][j] = 0ull;

    // prefetch k-tile 0
    float4 pa0 = *(const float4*)&Wm[(m0 + am) * 256 + ak];
    float4 pa1 = *(const float4*)&Wm[(m0 + am) * 256 + ak + 4];
    float4 pb0 = *(const float4*)&g_att[bk * PIXTOT + n0 + bn];
    float4 pb1 = *(const float4*)&g_att[bk * PIXTOT + n0 + bn + 4];

    for (int k0 = 0; k0 < 256; k0 += 16) {
        // commit prefetched tile to smem (A transposed to [k][m])
        As[(ak + 0) * PSROW + am] = pa0.x;
        As[(ak + 1) * PSROW + am] = pa0.y;
        As[(ak + 2) * PSROW + am] = pa0.z;
        As[(ak + 3) * PSROW + am] = pa0.w;
        As[(ak + 4) * PSROW + am] = pa1.x;
        As[(ak + 5) * PSROW + am] = pa1.y;
        As[(ak + 6) * PSROW + am] = pa1.z;
        As[(ak + 7) * PSROW + am] = pa1.w;
        *(float4*)&Bs[bk * PSROW + bn]     = pb0;
        *(float4*)&Bs[bk * PSROW + bn + 4] = pb1;
        __syncthreads();

        // prefetch next k-tile while FMAs run
        if (k0 < 240) {
            pa0 = *(const float4*)&Wm[(m0 + am) * 256 + k0 + 16 + ak];
            pa1 = *(const float4*)&Wm[(m0 + am) * 256 + k0 + 16 + ak + 4];
            pb0 = *(const float4*)&g_att[(k0 + 16 + bk) * PIXTOT + n0 + bn];
            pb1 = *(const float4*)&g_att[(k0 + 16 + bk) * PIXTOT + n0 + bn + 4];
        }

        #pragma unroll
        for (int k = 0; k < 16; ++k) {
            float4 a0 = *(const float4*)&As[k * PSROW + ty * 4];
            float4 a1 = *(const float4*)&As[k * PSROW + 64 + ty * 4];
            ulonglong2 b01 = *(const ulonglong2*)&Bs[k * PSROW + tx * 4];
            ulonglong2 b23 = *(const ulonglong2*)&Bs[k * PSROW + 64 + tx * 4];
            float av[8] = {a0.x, a0.y, a0.z, a0.w, a1.x, a1.y, a1.z, a1.w};
            #pragma unroll
            for (int i = 0; i < 8; ++i) {
                ull pav = pack2(av[i], av[i]);
                ffma2(acc2[i][0], pav, b01.x);
                ffma2(acc2[i][1], pav, b01.y);
                ffma2(acc2[i][2], pav, b23.x);
                ffma2(acc2[i][3], pav, b23.y);
            }
        }
        __syncthreads();
    }

    #pragma unroll
    for (int i = 0; i < 8; ++i) {
        int m = m0 + ((i < 4) ? (ty * 4 + i) : (64 + ty * 4 + i - 4));
        float bias = __ldg(&pb[m]);
        float* rp = &g_proj[m * PIXTOT + n0];
        float2 c0 = unpack2(acc2[i][0]);
        float2 c1 = unpack2(acc2[i][1]);
        float2 c2 = unpack2(acc2[i][2]);
        float2 c3 = unpack2(acc2[i][3]);
        float4 r0 = make_float4(c0.x + bias, c0.y + bias, c1.x + bias, c1.y + bias);
        float4 r1 = make_float4(c2.x + bias, c2.y + bias, c3.x + bias, c3.y + bias);
        *(float4*)&rp[tx * 4]      = r0;
        *(float4*)&rp[64 + tx * 4] = r1;
    }
}

// ---------------- K4: inverse wavelet (transposed depthwise 2x2) ------------
__global__ void iwt_kernel(const float* __restrict__ iwt, float* __restrict__ out) {
    int xo = threadIdx.x;          // 0..127
    int y  = blockIdx.x;           // 0..127
    int bc = blockIdx.y;           // 0..511
    int b  = bc >> 8, c = bc & 255;

    int base = (bc * H2 + y) * H2 + xo;
    float lh = g_lh[base], hl = g_hl[base], hh = g_hh[base];

    int wy = y >> 3, pyy = y & 7, wx = xo >> 3, pxx = xo & 7;
    int wdx = (b * 16 + wy) * 16 + wx;
    float ll = g_proj[c * PIXTOT + wdx * 64 + pyy * 8 + pxx];

    const float4 f0 = __ldg((const float4*)&iwt[(4 * c + 0) * 4]);
    const float4 f1 = __ldg((const float4*)&iwt[(4 * c + 1) * 4]);
    const float4 f2 = __ldg((const float4*)&iwt[(4 * c + 2) * 4]);
    const float4 f3 = __ldg((const float4*)&iwt[(4 * c + 3) * 4]);

    int ob = (bc * RESV + 2 * y) * RESV + 2 * xo;
    float2 r0 = make_float2(ll * f0.x + lh * f1.x + hl * f2.x + hh * f3.x,
                            ll * f0.y + lh * f1.y + hl * f2.y + hh * f3.y);
    float2 r1 = make_float2(ll * f0.z + lh * f1.z + hl * f2.z + hh * f3.z,
                            ll * f0.w + lh * f1.w + hl * f2.w + hh * f3.w);
    *(float2*)&out[ob]        = r0;
    *(float2*)&out[ob + RESV] = r1;
}

// ---------------- launch ----------------------------------------------------
extern "C" void kernel_launch(void* const* d_in, const int* in_sizes, int n_in,
                              void* d_out, int out_size) {
    const float* x    = (const float*)d_in[0];
    const float* wtf  = (const float*)d_in[1];
    const float* iwtf = (const float*)d_in[2];
    const float* dww  = (const float*)d_in[3];
    const float* dwb  = (const float*)d_in[4];
    const float* pw   = (const float*)d_in[5];
    const float* pb   = (const float*)d_in[6];
    const float* ab   = (const float*)d_in[7];
    const int*   bidx = (const int*)d_in[8];
    float* out = (float*)d_out;

    bias_kernel<<<128, 256>>>(ab, bidx);
    wt_kernel<<<dim3(128, 512), 128>>>(x, wtf);
    attn_mat_kernel<<<4096, 256>>>(dww, dwb);
    attn_av_kernel<<<512, 256>>>();
    proj_gemm<<<dim3(256, 2), 256>>>(pw, pb);
    iwt_kernel<<<dim3(128, 512), 128>>>(iwtf, out);
}

// round 9
// speedup vs baseline: 1.3060x; 1.0100x over previous
#include <cuda_runtime.h>

#define DIMC 256
#define RESV 256
#define H2 128
#define HEADS 8
#define HD 32
#define NPIX 64
#define NWIN 512
#define PIXTOT (NWIN * NPIX)   // 32768
#define ATTN_SCALE 0.17677669529663687f
#define SROW 68                // padded smem row stride (floats)
#define PSROW 132              // proj smem row stride (floats), 128-wide tiles

typedef unsigned long long ull;

// ---- packed fp32x2 helpers (FFMA2 — only reachable via PTX fma.rn.f32x2) ----
__device__ __forceinline__ void ffma2(ull& d, ull a, ull b) {
    asm("fma.rn.f32x2 %0, %1, %2, %0;" : "+l"(d) : "l"(a), "l"(b));
}
__device__ __forceinline__ ull pack2(float lo, float hi) {
    ull r; asm("mov.b64 %0, {%1, %2};" : "=l"(r) : "f"(lo), "f"(hi)); return r;
}
__device__ __forceinline__ float2 unpack2(ull v) {
    float2 r; asm("mov.b64 {%0, %1}, %2;" : "=f"(r.x), "=f"(r.y) : "l"(v)); return r;
}

// ---------------- scratch (static device allocations; no cudaMalloc) -------
__device__ float g_ll[2 * DIMC * H2 * H2];
__device__ float g_lh[2 * DIMC * H2 * H2];
__device__ float g_hl[2 * DIMC * H2 * H2];
__device__ float g_hh[2 * DIMC * H2 * H2];
__device__ float g_attn[NWIN * HEADS * NPIX * NPIX]; // softmax'd attn, [wh][m][n]
__device__ float g_att[DIMC * PIXTOT];    // relu(attention out), [c][pix]
__device__ float g_proj[DIMC * PIXTOT];   // proj out, [o][pix]
__device__ float g_bias[HEADS * NPIX * NPIX];

// ---------------- K0: expand attention bias table ---------------------------
__global__ void bias_kernel(const float* __restrict__ ab, const int* __restrict__ bidx) {
    int i = blockIdx.x * 256 + threadIdx.x;     // 32768 total
    int h = i >> 12;
    g_bias[i] = ab[h * 64 + bidx[i & 4095]];
}

// ---------------- K1: wavelet transform (depthwise 2x2 stride 2) -----------
__global__ void wt_kernel(const float* __restrict__ x, const float* __restrict__ wt) {
    int xo = threadIdx.x;          // 0..127
    int y  = blockIdx.x;           // 0..127
    int bc = blockIdx.y;           // 0..511 (b*256 + c)
    int c  = bc & 255;

    const float4 f0 = __ldg((const float4*)&wt[(4 * c + 0) * 4]);
    const float4 f1 = __ldg((const float4*)&wt[(4 * c + 1) * 4]);
    const float4 f2 = __ldg((const float4*)&wt[(4 * c + 2) * 4]);
    const float4 f3 = __ldg((const float4*)&wt[(4 * c + 3) * 4]);

    int ib = (bc * RESV + 2 * y) * RESV + 2 * xo;
    float2 p0 = *(const float2*)&x[ib];
    float2 p1 = *(const float2*)&x[ib + RESV];

    int ob = (bc * H2 + y) * H2 + xo;
    g_ll[ob] = p0.x * f0.x + p0.y * f0.y + p1.x * f0.z + p1.y * f0.w;
    g_lh[ob] = p0.x * f1.x + p0.y * f1.y + p1.x * f1.z + p1.y * f1.w;
    g_hl[ob] = p0.x * f2.x + p0.y * f2.y + p1.x * f2.z + p1.y * f2.w;
    g_hh[ob] = p0.x * f3.x + p0.y * f3.y + p1.x * f3.z + p1.y * f3.w;
}

// ---------------- K2a: attention matrices (all heads parallel) --------------
// One CTA per (window, head): q = dwconv5x5(lh), attn = softmax(qk*scale+bias)
// Output stored TRANSPOSED: g_attn[wh][m][n]
__global__ __launch_bounds__(256) void attn_mat_kernel(
    const float* __restrict__ dww, const float* __restrict__ dwb) {
    __shared__ float lh_s[HD * SROW];
    __shared__ float k_s[HD * SROW];
    __shared__ float q_s[HD * SROW];
    __shared__ float w_s[HD * 25];

    const int t  = threadIdx.x;
    const int wh = blockIdx.x;           // 0..4095
    const int w  = wh >> 3;
    const int h  = wh & 7;
    const int b  = w >> 8;
    const int wy = (w >> 4) & 15;
    const int wx = w & 15;
    const int dl = t >> 3;               // 0..31
    const int py = t & 7;                // 0..7

    // ---- load lh / hl window slices ----
    {
        int ch   = b * DIMC + h * HD + dl;
        int base = (ch * H2 + wy * 8 + py) * H2 + wx * 8;
        int o0   = dl * SROW + py * 8;
        *(float4*)&lh_s[o0]     = *(const float4*)&g_lh[base];
        *(float4*)&lh_s[o0 + 4] = *(const float4*)&g_lh[base + 4];
        *(float4*)&k_s[o0]      = *(const float4*)&g_hl[base];
        *(float4*)&k_s[o0 + 4]  = *(const float4*)&g_hl[base + 4];
    }
    for (int i = t; i < HD * 25; i += 256) w_s[i] = dww[h * HD * 25 + i];
    __syncthreads();

    // ---- q = depthwise 5x5 conv on lh (zero pad, per-window) ----
    {
        float accq[8];
        float bias0 = __ldg(&dwb[h * HD + dl]);
        #pragma unroll
        for (int px = 0; px < 8; ++px) accq[px] = bias0;
        #pragma unroll
        for (int u = 0; u < 5; ++u) {
            int yy = py + u - 2;
            if (yy >= 0 && yy < 8) {
                float4 r0 = *(const float4*)&lh_s[dl * SROW + yy * 8];
                float4 r1 = *(const float4*)&lh_s[dl * SROW + yy * 8 + 4];
                float r[8] = {r0.x, r0.y, r0.z, r0.w, r1.x, r1.y, r1.z, r1.w};
                #pragma unroll
                for (int v = 0; v < 5; ++v) {
                    float wv = w_s[dl * 25 + u * 5 + v];
                    #pragma unroll
                    for (int px = 0; px < 8; ++px) {
                        int xx = px + v - 2;
                        if (xx >= 0 && xx < 8)
                            accq[px] += r[xx] * wv;
                    }
                }
            }
        }
        #pragma unroll
        for (int px = 0; px < 8; ++px) q_s[dl * SROW + py * 8 + px] = accq[px];
    }
    __syncthreads();

    // ---- attn[n][m] = softmax_m(q.k * scale + bias) -> global (transposed) ----
    // QK inner product in packed f32x2 (pairs along m)
    {
        int n  = t >> 2;             // 0..63
        int mq = t & 3;              // 16 m's each
        ull acc2[8];
        #pragma unroll
        for (int i = 0; i < 8; ++i) acc2[i] = 0ull;

        #pragma unroll 4
        for (int d2 = 0; d2 < HD; ++d2) {
            float qd = q_s[d2 * SROW + n];
            ull pq = pack2(qd, qd);
            const float* kp = &k_s[d2 * SROW + mq * 16];
            ulonglong2 k01 = *(const ulonglong2*)(kp);       // m pairs (0,1),(2,3)
            ulonglong2 k23 = *(const ulonglong2*)(kp + 4);   // (4,5),(6,7)
            ulonglong2 k45 = *(const ulonglong2*)(kp + 8);
            ulonglong2 k67 = *(const ulonglong2*)(kp + 12);
            ffma2(acc2[0], pq, k01.x);
            ffma2(acc2[1], pq, k01.y);
            ffma2(acc2[2], pq, k23.x);
            ffma2(acc2[3], pq, k23.y);
            ffma2(acc2[4], pq, k45.x);
            ffma2(acc2[5], pq, k45.y);
            ffma2(acc2[6], pq, k67.x);
            ffma2(acc2[7], pq, k67.y);
        }

        float acc[16];
        #pragma unroll
        for (int i = 0; i < 8; ++i) {
            float2 u = unpack2(acc2[i]);
            acc[2 * i]     = u.x;
            acc[2 * i + 1] = u.y;
        }

        const float* bptr = &g_bias[h * 4096 + n * 64 + mq * 16];
        float mx = -1e30f;
        #pragma unroll
        for (int mi = 0; mi < 16; ++mi) {
            acc[mi] = acc[mi] * ATTN_SCALE + __ldg(&bptr[mi]);
            mx = fmaxf(mx, acc[mi]);
        }
        mx = fmaxf(mx, __shfl_xor_sync(0xffffffffu, mx, 1));
        mx = fmaxf(mx, __shfl_xor_sync(0xffffffffu, mx, 2));
        float s = 0.f;
        #pragma unroll
        for (int mi = 0; mi < 16; ++mi) {
            float e = __expf(acc[mi] - mx);
            acc[mi] = e;
            s += e;
        }
        s += __shfl_xor_sync(0xffffffffu, s, 1);
        s += __shfl_xor_sync(0xffffffffu, s, 2);
        float inv = 1.f / s;

        float* op = &g_attn[wh * 4096];
        #pragma unroll
        for (int mi = 0; mi < 16; ++mi)
            op[(mq * 16 + mi) * 64 + n] = acc[mi] * inv;   // [m][n]
    }
}

// ---------------- K2b: sequential AV chain, 2 CTAs per window (d-split) ----
// CTA handles 16 d-rows through all 8 heads. 128 threads, 4 warps.
// The head recurrence v_h[d] = o_{h-1}[d] + ll_h[d] is elementwise in d,
// so the d-dimension splits across CTAs with no communication.
__global__ __launch_bounds__(128) void attn_av_kernel() {
    __shared__ float v_s[16 * NPIX];        // 4KB
    __shared__ float o_s[16 * NPIX];        // 4KB
    __shared__ float attn_s[NPIX * NPIX];   // 16KB

    const int t    = threadIdx.x;           // 0..127
    const int wc   = blockIdx.x;            // 0..1023
    const int w    = wc >> 1;
    const int dbase = (wc & 1) * 16;        // d-half of this CTA
    const int b  = w >> 8;
    const int wy = (w >> 4) & 15;
    const int wx = w & 15;
    const int wp   = t >> 5;                // warp 0..3 -> local d rows 4wp..4wp+3
    const int lane = t & 31;                // n and n+32

    float4 pa[8];   // prefetched attn chunk (full 64x64 tile / 128 threads)
    float4 pl[2];   // prefetched ll chunk   (16x64 slab / 128 threads)

    {
        const float* ap = &g_attn[(w * 8 + 0) * 4096];
        #pragma unroll
        for (int i = 0; i < 8; ++i)
            pa[i] = *(const float4*)&ap[(t + 128 * i) * 4];
        #pragma unroll
        for (int i = 0; i < 2; ++i) {
            int c  = t + 128 * i;            // 0..255
            int d  = c >> 4;                 // 0..15 local
            int m0 = (c & 15) * 4;
            int ch = b * DIMC + 0 * HD + dbase + d;
            pl[i] = *(const float4*)&g_ll[(ch * H2 + wy * 8 + (m0 >> 3)) * H2
                                          + wx * 8 + (m0 & 7)];
        }
    }

    for (int h = 0; h < HEADS; ++h) {
        __syncthreads();

        #pragma unroll
        for (int i = 0; i < 8; ++i)
            *(float4*)&attn_s[(t + 128 * i) * 4] = pa[i];
        #pragma unroll
        for (int i = 0; i < 2; ++i) {
            int c = t + 128 * i;
            float4 v4 = pl[i];
            if (h > 0) {
                float4 o4 = *(const float4*)&o_s[c * 4];
                v4.x += o4.x; v4.y += o4.y; v4.z += o4.z; v4.w += o4.w;
                int d  = c >> 4;
                int m0 = (c & 15) * 4;
                float4 r = make_float4(fmaxf(o4.x, 0.f), fmaxf(o4.y, 0.f),
                                       fmaxf(o4.z, 0.f), fmaxf(o4.w, 0.f));
                *(float4*)&g_att[((h - 1) * HD + dbase + d) * PIXTOT + w * 64 + m0] = r;
            }
            *(float4*)&v_s[c * 4] = v4;
        }

        if (h < HEADS - 1) {
            const float* ap = &g_attn[(w * 8 + h + 1) * 4096];
            #pragma unroll
            for (int i = 0; i < 8; ++i)
                pa[i] = *(const float4*)&ap[(t + 128 * i) * 4];
            #pragma unroll
            for (int i = 0; i < 2; ++i) {
                int c  = t + 128 * i;
                int d  = c >> 4;
                int m0 = (c & 15) * 4;
                int ch = b * DIMC + (h + 1) * HD + dbase + d;
                pl[i] = *(const float4*)&g_ll[(ch * H2 + wy * 8 + (m0 >> 3)) * H2
                                              + wx * 8 + (m0 & 7)];
            }
        }
        __syncthreads();

        // ---- out[d][n] = sum_m v[d][m] * attn_t[m][n], packed pairs along m ----
        ull acc2[4][2];
        #pragma unroll
        for (int j = 0; j < 4; ++j) { acc2[j][0] = 0ull; acc2[j][1] = 0ull; }

        #pragma unroll
        for (int m = 0; m < 64; m += 4) {
            ulonglong2 va0 = *(const ulonglong2*)&v_s[(4 * wp + 0) * 64 + m];
            ulonglong2 va1 = *(const ulonglong2*)&v_s[(4 * wp + 1) * 64 + m];
            ulonglong2 va2 = *(const ulonglong2*)&v_s[(4 * wp + 2) * 64 + m];
            ulonglong2 va3 = *(const ulonglong2*)&v_s[(4 * wp + 3) * 64 + m];
            float b0l = attn_s[(m + 0) * 64 + lane];
            float b1l = attn_s[(m + 1) * 64 + lane];
            float b2l = attn_s[(m + 2) * 64 + lane];
            float b3l = attn_s[(m + 3) * 64 + lane];
            float b0h = attn_s[(m + 0) * 64 + lane + 32];
            float b1h = attn_s[(m + 1) * 64 + lane + 32];
            float b2h = attn_s[(m + 2) * 64 + lane + 32];
            float b3h = attn_s[(m + 3) * 64 + lane + 32];
            ull bl01 = pack2(b0l, b1l), bl23 = pack2(b2l, b3l);
            ull bh01 = pack2(b0h, b1h), bh23 = pack2(b2h, b3h);
            ffma2(acc2[0][0], va0.x, bl01); ffma2(acc2[0][0], va0.y, bl23);
            ffma2(acc2[1][0], va1.x, bl01); ffma2(acc2[1][0], va1.y, bl23);
            ffma2(acc2[2][0], va2.x, bl01); ffma2(acc2[2][0], va2.y, bl23);
            ffma2(acc2[3][0], va3.x, bl01); ffma2(acc2[3][0], va3.y, bl23);
            ffma2(acc2[0][1], va0.x, bh01); ffma2(acc2[0][1], va0.y, bh23);
            ffma2(acc2[1][1], va1.x, bh01); ffma2(acc2[1][1], va1.y, bh23);
            ffma2(acc2[2][1], va2.x, bh01); ffma2(acc2[2][1], va2.y, bh23);
            ffma2(acc2[3][1], va3.x, bh01); ffma2(acc2[3][1], va3.y, bh23);
        }
        #pragma unroll
        for (int j = 0; j < 4; ++j) {
            float2 u0 = unpack2(acc2[j][0]);
            float2 u1 = unpack2(acc2[j][1]);
            o_s[(4 * wp + j) * 64 + lane]      = u0.x + u0.y;
            o_s[(4 * wp + j) * 64 + lane + 32] = u1.x + u1.y;
        }
    }

    __syncthreads();
    #pragma unroll
    for (int i = 0; i < 2; ++i) {
        int c  = t + 128 * i;
        int d  = c >> 4;
        int m0 = (c & 15) * 4;
        float4 o4 = *(const float4*)&o_s[c * 4];
        float4 r = make_float4(fmaxf(o4.x, 0.f), fmaxf(o4.y, 0.f),
                               fmaxf(o4.z, 0.f), fmaxf(o4.w, 0.f));
        *(float4*)&g_att[(7 * HD + dbase + d) * PIXTOT + w * 64 + m0] = r;
    }
}

// ---------------- K3: proj GEMM  C[256,32768] = W[256,256] @ A + bias ------
// 128x128 tile, 8x8 per-thread micro-tile (packed f32x2 along n),
// register-prefetch pipeline
__global__ __launch_bounds__(256) void proj_gemm(
    const float* __restrict__ Wm, const float* __restrict__ pb) {
    __shared__ float As[16 * PSROW];   // As[k][m], m-tile 128
    __shared__ float Bs[16 * PSROW];   // Bs[k][n], n-tile 128

    const int t  = threadIdx.x;
    const int n0 = blockIdx.x * 128;   // 256 tiles
    const int m0 = blockIdx.y * 128;   // 2 tiles
    const int tx = t & 15, ty = t >> 4;

    // load mapping
    const int am = t >> 1;             // 0..127
    const int ak = (t & 1) * 8;        // 0 or 8
    const int bk = t >> 4;             // 0..15
    const int bn = (t & 15) * 8;       // 0..120

    ull acc2[8][4];                    // [mi][n-pair]: pairs (0,1)(2,3)(64,65)(66,67)+tx*4
    #pragma unroll
    for (int i = 0; i < 8; ++i)
        #pragma unroll
        for (int j = 0; j < 4; ++j) acc2[i][j] = 0ull;

    // prefetch k-tile 0
    float4 pa0 = *(const float4*)&Wm[(m0 + am) * 256 + ak];
    float4 pa1 = *(const float4*)&Wm[(m0 + am) * 256 + ak + 4];
    float4 pb0 = *(const float4*)&g_att[bk * PIXTOT + n0 + bn];
    float4 pb1 = *(const float4*)&g_att[bk * PIXTOT + n0 + bn + 4];

    for (int k0 = 0; k0 < 256; k0 += 16) {
        // commit prefetched tile to smem (A transposed to [k][m])
        As[(ak + 0) * PSROW + am] = pa0.x;
        As[(ak + 1) * PSROW + am] = pa0.y;
        As[(ak + 2) * PSROW + am] = pa0.z;
        As[(ak + 3) * PSROW + am] = pa0.w;
        As[(ak + 4) * PSROW + am] = pa1.x;
        As[(ak + 5) * PSROW + am] = pa1.y;
        As[(ak + 6) * PSROW + am] = pa1.z;
        As[(ak + 7) * PSROW + am] = pa1.w;
        *(float4*)&Bs[bk * PSROW + bn]     = pb0;
        *(float4*)&Bs[bk * PSROW + bn + 4] = pb1;
        __syncthreads();

        // prefetch next k-tile while FMAs run
        if (k0 < 240) {
            pa0 = *(const float4*)&Wm[(m0 + am) * 256 + k0 + 16 + ak];
            pa1 = *(const float4*)&Wm[(m0 + am) * 256 + k0 + 16 + ak + 4];
            pb0 = *(const float4*)&g_att[(k0 + 16 + bk) * PIXTOT + n0 + bn];
            pb1 = *(const float4*)&g_att[(k0 + 16 + bk) * PIXTOT + n0 + bn + 4];
        }

        #pragma unroll
        for (int k = 0; k < 16; ++k) {
            float4 a0 = *(const float4*)&As[k * PSROW + ty * 4];
            float4 a1 = *(const float4*)&As[k * PSROW + 64 + ty * 4];
            ulonglong2 b01 = *(const ulonglong2*)&Bs[k * PSROW + tx * 4];
            ulonglong2 b23 = *(const ulonglong2*)&Bs[k * PSROW + 64 + tx * 4];
            float av[8] = {a0.x, a0.y, a0.z, a0.w, a1.x, a1.y, a1.z, a1.w};
            #pragma unroll
            for (int i = 0; i < 8; ++i) {
                ull pav = pack2(av[i], av[i]);
                ffma2(acc2[i][0], pav, b01.x);
                ffma2(acc2[i][1], pav, b01.y);
                ffma2(acc2[i][2], pav, b23.x);
                ffma2(acc2[i][3], pav, b23.y);
            }
        }
        __syncthreads();
    }

    #pragma unroll
    for (int i = 0; i < 8; ++i) {
        int m = m0 + ((i < 4) ? (ty * 4 + i) : (64 + ty * 4 + i - 4));
        float bias = __ldg(&pb[m]);
        float* rp = &g_proj[m * PIXTOT + n0];
        float2 c0 = unpack2(acc2[i][0]);
        float2 c1 = unpack2(acc2[i][1]);
        float2 c2 = unpack2(acc2[i][2]);
        float2 c3 = unpack2(acc2[i][3]);
        float4 r0 = make_float4(c0.x + bias, c0.y + bias, c1.x + bias, c1.y + bias);
        float4 r1 = make_float4(c2.x + bias, c2.y + bias, c3.x + bias, c3.y + bias);
        *(float4*)&rp[tx * 4]      = r0;
        *(float4*)&rp[64 + tx * 4] = r1;
    }
}

// ---------------- K4: inverse wavelet (transposed depthwise 2x2) ------------
__global__ void iwt_kernel(const float* __restrict__ iwt, float* __restrict__ out) {
    int xo = threadIdx.x;          // 0..127
    int y  = blockIdx.x;           // 0..127
    int bc = blockIdx.y;           // 0..511
    int b  = bc >> 8, c = bc & 255;

    int base = (bc * H2 + y) * H2 + xo;
    float lh = g_lh[base], hl = g_hl[base], hh = g_hh[base];

    int wy = y >> 3, pyy = y & 7, wx = xo >> 3, pxx = xo & 7;
    int wdx = (b * 16 + wy) * 16 + wx;
    float ll = g_proj[c * PIXTOT + wdx * 64 + pyy * 8 + pxx];

    const float4 f0 = __ldg((const float4*)&iwt[(4 * c + 0) * 4]);
    const float4 f1 = __ldg((const float4*)&iwt[(4 * c + 1) * 4]);
    const float4 f2 = __ldg((const float4*)&iwt[(4 * c + 2) * 4]);
    const float4 f3 = __ldg((const float4*)&iwt[(4 * c + 3) * 4]);

    int ob = (bc * RESV + 2 * y) * RESV + 2 * xo;
    float2 r0 = make_float2(ll * f0.x + lh * f1.x + hl * f2.x + hh * f3.x,
                            ll * f0.y + lh * f1.y + hl * f2.y + hh * f3.y);
    float2 r1 = make_float2(ll * f0.z + lh * f1.z + hl * f2.z + hh * f3.z,
                            ll * f0.w + lh * f1.w + hl * f2.w + hh * f3.w);
    *(float2*)&out[ob]        = r0;
    *(float2*)&out[ob + RESV] = r1;
}

// ---------------- launch ----------------------------------------------------
extern "C" void kernel_launch(void* const* d_in, const int* in_sizes, int n_in,
                              void* d_out, int out_size) {
    const float* x    = (const float*)d_in[0];
    const float* wtf  = (const float*)d_in[1];
    const float* iwtf = (const float*)d_in[2];
    const float* dww  = (const float*)d_in[3];
    const float* dwb  = (const float*)d_in[4];
    const float* pw   = (const float*)d_in[5];
    const float* pb   = (const float*)d_in[6];
    const float* ab   = (const float*)d_in[7];
    const int*   bidx = (const int*)d_in[8];
    float* out = (float*)d_out;

    bias_kernel<<<128, 256>>>(ab, bidx);
    wt_kernel<<<dim3(128, 512), 128>>>(x, wtf);
    attn_mat_kernel<<<4096, 256>>>(dww, dwb);
    attn_av_kernel<<<1024, 128>>>();
    proj_gemm<<<dim3(256, 2), 256>>>(pw, pb);
    iwt_kernel<<<dim3(128, 512), 128>>>(iwtf, out);
}